// round 2
// baseline (speedup 1.0000x reference)
#include <cuda_runtime.h>
#include <math.h>

#define B_    4
#define N_    4096
#define F_    512
#define C_    64
#define M_TOT (B_ * N_)   // 16384

// Scratch (allocation-free: static __device__ globals)
__device__ float g_f[M_TOT * C_];                       //  4 MiB
__device__ float g_g[M_TOT * C_];                       //  4 MiB
__device__ float g_h[(size_t)M_TOT * F_];               // 32 MiB
__device__ float g_s[(size_t)M_TOT * N_];               // 256 MiB
__device__ float g_rs[M_TOT];

// ---------------------------------------------------------------------------
// Generic tiled SGEMM: C[M,N] = A[M,K] @ B[K,N]
//   TRANSB: B physical is [N,K] row-major (used for f @ g^T, ldB == K)
//   MODE 1: C = relu(acc + bias[n])
//   MODE 2: C = acc (raw scores)
//   MODE 3: C = gamma[n] * (acc / rowsum[m]) + vres[m,n]
// Batched via blockIdx.z with element strides sA/sB/sC/sV (rowsum stride = M).
// ---------------------------------------------------------------------------
template <bool TRANSB, int MODE>
__global__ __launch_bounds__(256) void sgemm_k(
    const float* __restrict__ A, const float* __restrict__ Bm,
    float* __restrict__ C, int M, int N, int K,
    const float* __restrict__ bias,
    const float* __restrict__ gamma, const float* __restrict__ vres,
    const float* __restrict__ rowsum,
    long sA, long sB, long sC, long sV)
{
    constexpr int BM = 128, BN = 128, BK = 16;
    constexpr int TM = 8, TN = 8;

    __shared__ float As[BK][BM + 4];
    __shared__ float Bs[BK][BN + 4];

    const int bz = blockIdx.z;
    A  += (size_t)bz * sA;
    Bm += (size_t)bz * sB;
    C  += (size_t)bz * sC;
    const float* vres_b = (MODE == 3) ? vres + (size_t)bz * sV : nullptr;
    const float* rs_b   = (MODE == 3) ? rowsum + (size_t)bz * M : nullptr;

    const int tid = threadIdx.x;          // 0..255
    const int tx = tid & 15;              // 0..15
    const int ty = tid >> 4;              // 0..15
    const int m0 = blockIdx.y * BM;
    const int n0 = blockIdx.x * BN;

    float acc[TM][TN];
#pragma unroll
    for (int i = 0; i < TM; i++)
#pragma unroll
        for (int j = 0; j < TN; j++) acc[i][j] = 0.f;

    for (int k0 = 0; k0 < K; k0 += BK) {
        // --- A tile [BM x BK] -> As[k][m] (transposed store) ---
#pragma unroll
        for (int l = 0; l < 2; l++) {
            int idx = tid + l * 256;      // 0..511
            int r   = idx >> 2;           // 0..127 (m)
            int c4  = idx & 3;            // 0..3   (k/4)
            int gr  = m0 + r;
            float4 v = make_float4(0.f, 0.f, 0.f, 0.f);
            if (gr < M)
                v = *reinterpret_cast<const float4*>(&A[(size_t)gr * K + k0 + c4 * 4]);
            As[c4 * 4 + 0][r] = v.x;
            As[c4 * 4 + 1][r] = v.y;
            As[c4 * 4 + 2][r] = v.z;
            As[c4 * 4 + 3][r] = v.w;
        }
        // --- B tile [BK x BN] -> Bs[k][n] ---
        if (!TRANSB) {
#pragma unroll
            for (int l = 0; l < 2; l++) {
                int idx = tid + l * 256;
                int r   = idx >> 5;       // 0..15 (k)
                int c4  = idx & 31;       // 0..31 (n/4)
                int gc  = n0 + c4 * 4;
                float4 v = make_float4(0.f, 0.f, 0.f, 0.f);
                if (gc < N)
                    v = *reinterpret_cast<const float4*>(&Bm[(size_t)(k0 + r) * N + gc]);
                *reinterpret_cast<float4*>(&Bs[r][c4 * 4]) = v;
            }
        } else {
            // logical B[k][n] = Bm[n*K + k]
#pragma unroll
            for (int l = 0; l < 2; l++) {
                int idx = tid + l * 256;
                int r   = idx >> 2;       // 0..127 (n)
                int c4  = idx & 3;        // 0..3   (k/4)
                int gn  = n0 + r;
                float4 v = make_float4(0.f, 0.f, 0.f, 0.f);
                if (gn < N)
                    v = *reinterpret_cast<const float4*>(&Bm[(size_t)gn * K + k0 + c4 * 4]);
                Bs[c4 * 4 + 0][r] = v.x;
                Bs[c4 * 4 + 1][r] = v.y;
                Bs[c4 * 4 + 2][r] = v.z;
                Bs[c4 * 4 + 3][r] = v.w;
            }
        }
        __syncthreads();

#pragma unroll
        for (int k = 0; k < BK; k++) {
            float a[TM], b[TN];
#pragma unroll
            for (int i = 0; i < TM; i++) a[i] = As[k][ty * TM + i];
#pragma unroll
            for (int j = 0; j < TN; j++) b[j] = Bs[k][tx * TN + j];
#pragma unroll
            for (int i = 0; i < TM; i++)
#pragma unroll
                for (int j = 0; j < TN; j++)
                    acc[i][j] = fmaf(a[i], b[j], acc[i][j]);
        }
        __syncthreads();
    }

    // --- Epilogue ---
#pragma unroll
    for (int i = 0; i < TM; i++) {
        int gr = m0 + ty * TM + i;
        if (gr >= M) continue;
        float inv = 1.f;
        if (MODE == 3) inv = 1.f / rs_b[gr];
#pragma unroll
        for (int j = 0; j < TN; j++) {
            int gc = n0 + tx * TN + j;
            if (gc >= N) continue;
            float v = acc[i][j];
            if (MODE == 1)      v = fmaxf(v + bias[gc], 0.f);
            else if (MODE == 3) v = fmaf(gamma[gc], v * inv, vres_b[(size_t)gr * N + gc]);
            C[(size_t)gr * N + gc] = v;
        }
    }
}

// ---------------------------------------------------------------------------
// Row softmax over s (row length N_ = 4096), stores e^(x-max) in place and the
// row sum (normalization folded into the s@h GEMM epilogue).
// ---------------------------------------------------------------------------
__global__ __launch_bounds__(256) void softmax_k(float* __restrict__ s,
                                                 float* __restrict__ rs)
{
    const int row = blockIdx.x;                 // 0..M_TOT-1
    float* p = s + (size_t)row * N_;
    __shared__ float buf[N_];
    __shared__ float red[256];
    const int tid = threadIdx.x;

    float m = -INFINITY;
    for (int i = tid; i < N_; i += 256) {
        float v = p[i];
        buf[i] = v;
        m = fmaxf(m, v);
    }
    red[tid] = m;
    __syncthreads();
    for (int st = 128; st > 0; st >>= 1) {
        if (tid < st) red[tid] = fmaxf(red[tid], red[tid + st]);
        __syncthreads();
    }
    const float mall = red[0];
    __syncthreads();

    float sum = 0.f;
    for (int i = tid; i < N_; i += 256) {
        float e = __expf(buf[i] - mall);
        p[i] = e;
        sum += e;
    }
    red[tid] = sum;
    __syncthreads();
    for (int st = 128; st > 0; st >>= 1) {
        if (tid < st) red[tid] += red[tid + st];
        __syncthreads();
    }
    if (tid == 0) rs[row] = red[0];
}

// ---------------------------------------------------------------------------
extern "C" void kernel_launch(void* const* d_in, const int* in_sizes, int n_in,
                              void* d_out, int out_size)
{
    const float* V  = (const float*)d_in[0];
    const float* Wf = (const float*)d_in[1];
    const float* bf = (const float*)d_in[2];
    const float* Wg = (const float*)d_in[3];
    const float* bg = (const float*)d_in[4];
    const float* Wh = (const float*)d_in[5];
    const float* bh = (const float*)d_in[6];
    const float* gm = (const float*)d_in[7];
    float* out = (float*)d_out;

    float *fP, *gP, *hP, *sP, *rsP;
    cudaGetSymbolAddress((void**)&fP,  g_f);
    cudaGetSymbolAddress((void**)&gP,  g_g);
    cudaGetSymbolAddress((void**)&hP,  g_h);
    cudaGetSymbolAddress((void**)&sP,  g_s);
    cudaGetSymbolAddress((void**)&rsP, g_rs);

    dim3 blk(256);

    // Projections: f = relu(V@Wf+bf), g = relu(V@Wg+bg), h = relu(V@Wh+bh)
    sgemm_k<false, 1><<<dim3(1, 128, 1), blk>>>(V, Wf, fP, M_TOT, C_, F_,
                                                bf, nullptr, nullptr, nullptr, 0, 0, 0, 0);
    sgemm_k<false, 1><<<dim3(1, 128, 1), blk>>>(V, Wg, gP, M_TOT, C_, F_,
                                                bg, nullptr, nullptr, nullptr, 0, 0, 0, 0);
    sgemm_k<false, 1><<<dim3(4, 128, 1), blk>>>(V, Wh, hP, M_TOT, F_, F_,
                                                bh, nullptr, nullptr, nullptr, 0, 0, 0, 0);

    // scores = f @ g^T  (per batch; raw)
    sgemm_k<true, 2><<<dim3(32, 32, B_), blk>>>(fP, gP, sP, N_, N_, C_,
                                                nullptr, nullptr, nullptr, nullptr,
                                                (long)N_ * C_, (long)N_ * C_,
                                                (long)N_ * N_, 0);

    // softmax (unnormalized exp + rowsum)
    softmax_k<<<M_TOT, blk>>>(sP, rsP);

    // out = gamma * (e@h / rowsum) + V  (per batch)
    sgemm_k<false, 3><<<dim3(4, 32, B_), blk>>>(sP, hP, out, N_, F_, N_,
                                                nullptr, gm, V, rsP,
                                                (long)N_ * N_, (long)N_ * F_,
                                                (long)N_ * F_, (long)N_ * F_);
}

// round 5
// speedup vs baseline: 4.0573x; 4.0573x over previous
// R5: identical to R4 candidate — R4 failed with a pre-main harness device-init
// error ("device busy or unavailable"), so this is a clean re-bench to get a
// real measurement of the mma.sync tf32 rewrite.
#include <cuda_runtime.h>
#include <cstdint>
#include <math.h>

#define B_    4
#define N_    4096
#define F_    512
#define C_    64
#define M_TOT (B_ * N_)   // 16384

// ---------------- scratch (allocation-free) ----------------
__device__ float g_Vr[(size_t)M_TOT * F_];        // 32 MiB (tf32-rounded V)
__device__ float g_f[M_TOT * C_];                 //  4 MiB
__device__ float g_g[M_TOT * C_];                 //  4 MiB
__device__ float g_h[(size_t)M_TOT * F_];         // 32 MiB, [B][N][F]
__device__ float g_hT[(size_t)M_TOT * F_];        // 32 MiB, [B][F][N]
__device__ float g_s[(size_t)M_TOT * N_];         // 256 MiB
__device__ float g_rs[M_TOT];
__device__ float g_wfT[C_ * F_];
__device__ float g_wgT[C_ * F_];
__device__ float g_whT[F_ * F_];

// ---------------- helpers ----------------
__device__ __forceinline__ float tf32r(float x) {
    uint32_t u;
    asm("cvt.rna.tf32.f32 %0, %1;" : "=r"(u) : "f"(x));
    return __uint_as_float(u);
}
__device__ __forceinline__ uint32_t smem_u32(const void* p) {
    uint32_t a;
    asm("{ .reg .u64 t; cvta.to.shared.u64 t, %1; cvt.u32.u64 %0, t; }" : "=r"(a) : "l"(p));
    return a;
}
#define CP16(dst, src) \
    asm volatile("cp.async.ca.shared.global [%0], [%1], 16;" :: "r"(dst), "l"(src))
#define CP_COMMIT() asm volatile("cp.async.commit_group;" ::: "memory")
#define CP_WAIT1()  asm volatile("cp.async.wait_group 1;" ::: "memory")
#define CP_WAIT0()  asm volatile("cp.async.wait_group 0;" ::: "memory")

__device__ __forceinline__ void mma_tf32(float* d, const float* a, const float* b) {
    asm volatile(
        "mma.sync.aligned.m16n8k8.row.col.f32.tf32.tf32.f32 "
        "{%0,%1,%2,%3}, {%4,%5,%6,%7}, {%8,%9}, {%0,%1,%2,%3};"
        : "+f"(d[0]), "+f"(d[1]), "+f"(d[2]), "+f"(d[3])
        : "r"(__float_as_uint(a[0])), "r"(__float_as_uint(a[1])),
          "r"(__float_as_uint(a[2])), "r"(__float_as_uint(a[3])),
          "r"(__float_as_uint(b[0])), "r"(__float_as_uint(b[1])));
}

// ---------------------------------------------------------------------------
// mma.sync tf32 GEMM: C[M, Nfull] = A[M,K] @ B^T, B stored [Nfull, K] K-major.
// Operands must already be tf32-rounded. CTA tile 128 x NT, BK=16, double-
// buffered cp.async. MODE 1: relu(acc+bias) tf32-rounded; MODE 2: raw;
// MODE 3: gamma[n]*(acc/rowsum[m]) + vres[m,n].
// ---------------------------------------------------------------------------
template <int NT, int MODE>
__global__ __launch_bounds__(256) void gemm_tc(
    const float* __restrict__ A, const float* __restrict__ Bm, float* __restrict__ C,
    int M, int Nfull, int K,
    const float* __restrict__ bias, const float* __restrict__ gamma,
    const float* __restrict__ vres, const float* __restrict__ rowsum,
    long sA, long sB, long sC, long sV)
{
    constexpr int BK = 16, LDA = 20;                 // row stride 20 floats
    constexpr int WN_WARPS = (NT >= 128) ? 4 : 2;
    constexpr int WM_WARPS = 8 / WN_WARPS;
    constexpr int WMT = 128 / WM_WARPS;              // 64 or 32
    constexpr int WNT = NT / WN_WARPS;               // 32
    constexpr int MF = WMT / 16, NF = WNT / 8;       // frags per warp
    constexpr int ASZ = 128 * LDA, BSZ = NT * LDA, BUF = ASZ + BSZ;

    extern __shared__ float sm[];
    const int tid = threadIdx.x, wid = tid >> 5, lane = tid & 31;
    const int lr = lane >> 2, lc = lane & 3;
    const int bz = blockIdx.z;

    A  += (size_t)bz * sA;
    Bm += (size_t)bz * sB;
    float* Cb = C + (size_t)bz * sC;
    const float* vres_b = vres + (size_t)bz * sV;
    const float* rs_b   = rowsum + (size_t)bz * (MODE == 3 ? M : 0);

    const int m0 = blockIdx.y * 128, n0 = blockIdx.x * NT;
    const int wm = wid % WM_WARPS, wn = wid / WM_WARPS;
    const uint32_t sbase = smem_u32(sm);

    float acc[MF][NF][4];
#pragma unroll
    for (int i = 0; i < MF; i++)
#pragma unroll
        for (int j = 0; j < NF; j++)
#pragma unroll
            for (int r = 0; r < 4; r++) acc[i][j][r] = 0.f;

    auto stage = [&](int k0, int buf) {
#pragma unroll
        for (int l = 0; l < 2; l++) {                       // A: 128 x 16
            int idx = tid + l * 256;
            int r = idx >> 2, q = idx & 3;
            CP16(sbase + (uint32_t)(buf * BUF + r * LDA + q * 4) * 4,
                 A + (size_t)(m0 + r) * K + k0 + q * 4);
        }
#pragma unroll
        for (int l = 0; l < NT / 64; l++) {                 // B: NT x 16
            int idx = tid + l * 256;
            int r = idx >> 2, q = idx & 3;
            CP16(sbase + (uint32_t)(buf * BUF + ASZ + r * LDA + q * 4) * 4,
                 Bm + (size_t)(n0 + r) * K + k0 + q * 4);
        }
        CP_COMMIT();
    };

    const int T = K / BK;
    stage(0, 0);
    for (int t = 0; t < T; t++) {
        if (t + 1 < T) { stage((t + 1) * BK, (t + 1) & 1); CP_WAIT1(); }
        else            { CP_WAIT0(); }
        __syncthreads();

        const float* As = sm + (t & 1) * BUF;
        const float* Bs = As + ASZ;
#pragma unroll
        for (int ks = 0; ks < 2; ks++) {
            const int kk = ks * 8 + lc;
            float a[MF][4], b[NF][2];
#pragma unroll
            for (int mf = 0; mf < MF; mf++) {
                const int r0 = (wm * WMT + mf * 16 + lr) * LDA;
                a[mf][0] = As[r0 + kk];
                a[mf][1] = As[r0 + 8 * LDA + kk];
                a[mf][2] = As[r0 + kk + 4];
                a[mf][3] = As[r0 + 8 * LDA + kk + 4];
            }
#pragma unroll
            for (int nf = 0; nf < NF; nf++) {
                const int r0 = (wn * WNT + nf * 8 + lr) * LDA;
                b[nf][0] = Bs[r0 + kk];
                b[nf][1] = Bs[r0 + kk + 4];
            }
#pragma unroll
            for (int mf = 0; mf < MF; mf++)
#pragma unroll
                for (int nf = 0; nf < NF; nf++)
                    mma_tf32(acc[mf][nf], a[mf], b[nf]);
        }
        __syncthreads();
    }

    // ---- epilogue (register fragments -> global) ----
    const int mb = m0 + wm * WMT, nb = n0 + wn * WNT;
#pragma unroll
    for (int mf = 0; mf < MF; mf++) {
        const int gr0 = mb + mf * 16 + lr, gr1 = gr0 + 8;
        float inv0 = 0.f, inv1 = 0.f;
        if (MODE == 3) { inv0 = 1.f / rs_b[gr0]; inv1 = 1.f / rs_b[gr1]; }
#pragma unroll
        for (int nf = 0; nf < NF; nf++) {
            const int gc = nb + nf * 8 + 2 * lc;
            const float* d = acc[mf][nf];
            if (MODE == 1) {
                Cb[(size_t)gr0 * Nfull + gc]     = tf32r(fmaxf(d[0] + bias[gc], 0.f));
                Cb[(size_t)gr0 * Nfull + gc + 1] = tf32r(fmaxf(d[1] + bias[gc + 1], 0.f));
                Cb[(size_t)gr1 * Nfull + gc]     = tf32r(fmaxf(d[2] + bias[gc], 0.f));
                Cb[(size_t)gr1 * Nfull + gc + 1] = tf32r(fmaxf(d[3] + bias[gc + 1], 0.f));
            } else if (MODE == 2) {
                Cb[(size_t)gr0 * Nfull + gc]     = d[0];
                Cb[(size_t)gr0 * Nfull + gc + 1] = d[1];
                Cb[(size_t)gr1 * Nfull + gc]     = d[2];
                Cb[(size_t)gr1 * Nfull + gc + 1] = d[3];
            } else {
                Cb[(size_t)gr0 * Nfull + gc] =
                    fmaf(gamma[gc], d[0] * inv0, vres_b[(size_t)gr0 * Nfull + gc]);
                Cb[(size_t)gr0 * Nfull + gc + 1] =
                    fmaf(gamma[gc + 1], d[1] * inv0, vres_b[(size_t)gr0 * Nfull + gc + 1]);
                Cb[(size_t)gr1 * Nfull + gc] =
                    fmaf(gamma[gc], d[2] * inv1, vres_b[(size_t)gr1 * Nfull + gc]);
                Cb[(size_t)gr1 * Nfull + gc + 1] =
                    fmaf(gamma[gc + 1], d[3] * inv1, vres_b[(size_t)gr1 * Nfull + gc + 1]);
            }
        }
    }
}

// ---------------------------------------------------------------------------
// Transpose (tf32-rounded): out[c][r] = round(in[r][c]). Batched by blockIdx.z.
// ---------------------------------------------------------------------------
__global__ void transpose_k(const float* __restrict__ in, float* __restrict__ out,
                            int R, int Ccols)
{
    __shared__ float t[32][33];
    in  += (size_t)blockIdx.z * R * Ccols;
    out += (size_t)blockIdx.z * R * Ccols;
    const int c0 = blockIdx.x * 32, r0 = blockIdx.y * 32;
    const int x = threadIdx.x, y = threadIdx.y;   // 32 x 8
#pragma unroll
    for (int i = 0; i < 32; i += 8)
        t[y + i][x] = in[(size_t)(r0 + y + i) * Ccols + c0 + x];
    __syncthreads();
#pragma unroll
    for (int i = 0; i < 32; i += 8)
        out[(size_t)(c0 + y + i) * R + r0 + x] = tf32r(t[x][y + i]);
}

// ---------------------------------------------------------------------------
// Elementwise tf32 rounding (float4)
// ---------------------------------------------------------------------------
__global__ __launch_bounds__(256) void round4_k(const float4* __restrict__ in,
                                                float4* __restrict__ out, int n4)
{
    int i = blockIdx.x * 256 + threadIdx.x;
    if (i < n4) {
        float4 v = in[i];
        v.x = tf32r(v.x); v.y = tf32r(v.y); v.z = tf32r(v.z); v.w = tf32r(v.w);
        out[i] = v;
    }
}

// ---------------------------------------------------------------------------
// Row softmax (unnormalized): stores tf32-rounded e^(x-max) in place + rowsum.
// ---------------------------------------------------------------------------
__global__ __launch_bounds__(256) void softmax_k(float* __restrict__ s,
                                                 float* __restrict__ rs)
{
    const int row = blockIdx.x;
    float* p = s + (size_t)row * N_;
    __shared__ float buf[N_];
    __shared__ float red[256];
    const int tid = threadIdx.x;

    float m = -INFINITY;
    for (int i = tid; i < N_; i += 256) {
        float v = p[i];
        buf[i] = v;
        m = fmaxf(m, v);
    }
    red[tid] = m;
    __syncthreads();
    for (int st = 128; st > 0; st >>= 1) {
        if (tid < st) red[tid] = fmaxf(red[tid], red[tid + st]);
        __syncthreads();
    }
    const float mall = red[0];
    __syncthreads();

    float sum = 0.f;
    for (int i = tid; i < N_; i += 256) {
        float e = __expf(buf[i] - mall);
        p[i] = tf32r(e);
        sum += e;
    }
    red[tid] = sum;
    __syncthreads();
    for (int st = 128; st > 0; st >>= 1) {
        if (tid < st) red[tid] += red[tid + st];
        __syncthreads();
    }
    if (tid == 0) rs[row] = red[0];
}

// ---------------------------------------------------------------------------
extern "C" void kernel_launch(void* const* d_in, const int* in_sizes, int n_in,
                              void* d_out, int out_size)
{
    const float* V  = (const float*)d_in[0];
    const float* Wf = (const float*)d_in[1];
    const float* bf = (const float*)d_in[2];
    const float* Wg = (const float*)d_in[3];
    const float* bg = (const float*)d_in[4];
    const float* Wh = (const float*)d_in[5];
    const float* bh = (const float*)d_in[6];
    const float* gm = (const float*)d_in[7];
    float* out = (float*)d_out;

    float *VrP, *fP, *gP, *hP, *hTP, *sP, *rsP, *wfT, *wgT, *whT;
    cudaGetSymbolAddress((void**)&VrP, g_Vr);
    cudaGetSymbolAddress((void**)&fP,  g_f);
    cudaGetSymbolAddress((void**)&gP,  g_g);
    cudaGetSymbolAddress((void**)&hP,  g_h);
    cudaGetSymbolAddress((void**)&hTP, g_hT);
    cudaGetSymbolAddress((void**)&sP,  g_s);
    cudaGetSymbolAddress((void**)&rsP, g_rs);
    cudaGetSymbolAddress((void**)&wfT, g_wfT);
    cudaGetSymbolAddress((void**)&wgT, g_wgT);
    cudaGetSymbolAddress((void**)&whT, g_whT);

    const int SM128 = 2 * (128 + 128) * 20 * 4;   // 40960 B
    const int SM64  = 2 * (128 + 64)  * 20 * 4;   // 30720 B
    dim3 blk(256);
    dim3 tb(32, 8);

    // tf32-round V; transpose+round weights to K-major [N, K]
    round4_k<<<(M_TOT * F_ / 4 + 255) / 256, blk>>>((const float4*)V, (float4*)VrP,
                                                    M_TOT * F_ / 4);
    transpose_k<<<dim3(C_ / 32, F_ / 32, 1), tb>>>(Wf, wfT, F_, C_);
    transpose_k<<<dim3(C_ / 32, F_ / 32, 1), tb>>>(Wg, wgT, F_, C_);
    transpose_k<<<dim3(F_ / 32, F_ / 32, 1), tb>>>(Wh, whT, F_, F_);

    // f = relu(V@Wf+bf), g = relu(V@Wg+bg)  [16384, 64]
    gemm_tc<64, 1><<<dim3(1, 128, 1), blk, SM64>>>(
        VrP, wfT, fP, M_TOT, C_, F_, bf, nullptr, fP, fP, 0, 0, 0, 0);
    gemm_tc<64, 1><<<dim3(1, 128, 1), blk, SM64>>>(
        VrP, wgT, gP, M_TOT, C_, F_, bg, nullptr, fP, fP, 0, 0, 0, 0);
    // h = relu(V@Wh+bh)  [16384, 512], then hT[b][f][n]
    gemm_tc<128, 1><<<dim3(4, 128, 1), blk, SM128>>>(
        VrP, whT, hP, M_TOT, F_, F_, bh, nullptr, fP, fP, 0, 0, 0, 0);
    transpose_k<<<dim3(F_ / 32, N_ / 32, B_), tb>>>(hP, hTP, N_, F_);

    // scores = f @ g^T per batch [4096, 4096]
    gemm_tc<128, 2><<<dim3(32, 32, B_), blk, SM128>>>(
        fP, gP, sP, N_, N_, C_, nullptr, nullptr, fP, fP,
        (long)N_ * C_, (long)N_ * C_, (long)N_ * N_, 0);

    // softmax (tf32-rounded exp + fp32 rowsum)
    softmax_k<<<M_TOT, blk>>>(sP, rsP);

    // out = gamma * (e @ h / rowsum) + V per batch [4096, 512]
    gemm_tc<128, 3><<<dim3(4, 32, B_), blk, SM128>>>(
        sP, hTP, out, N_, F_, N_, nullptr, gm, V, rsP,
        (long)N_ * N_, (long)F_ * N_, (long)N_ * F_, (long)N_ * F_);
}

// round 7
// speedup vs baseline: 5.8582x; 1.4438x over previous
// R6: s·h GEMM moved to bf16 m16n8k16 (2x HMMA rate; positive-sum averaging
// keeps error ~3e-4). V tf32-rounding folded into projection GEMMs (in-register).
// h written directly as transposed bf16. Scores stay tf32 (exp amplifies bf16
// score error ~4% -> disqualifying).
#include <cuda_runtime.h>
#include <cuda_bf16.h>
#include <cstdint>
#include <math.h>

#define B_    4
#define N_    4096
#define F_    512
#define C_    64
#define M_TOT (B_ * N_)   // 16384

// ---------------- scratch (allocation-free) ----------------
__device__ float g_f[M_TOT * C_];                        //  4 MiB (tf32-rounded)
__device__ float g_g[M_TOT * C_];                        //  4 MiB (tf32-rounded)
__device__ __nv_bfloat16 g_hT[(size_t)M_TOT * F_];       // 16 MiB, [B][F][N] bf16
__device__ float g_s[(size_t)M_TOT * N_];                // 256 MiB scores fp32
__device__ __nv_bfloat16 g_p[(size_t)M_TOT * N_];        // 128 MiB exp(bf16)
__device__ float g_rs[M_TOT];
__device__ float g_wfT[C_ * F_];
__device__ float g_wgT[C_ * F_];
__device__ float g_whT[F_ * F_];

// ---------------- helpers ----------------
__device__ __forceinline__ float tf32r(float x) {
    uint32_t u;
    asm("cvt.rna.tf32.f32 %0, %1;" : "=r"(u) : "f"(x));
    return __uint_as_float(u);
}
__device__ __forceinline__ uint32_t smem_u32(const void* p) {
    uint32_t a;
    asm("{ .reg .u64 t; cvta.to.shared.u64 t, %1; cvt.u32.u64 %0, t; }" : "=r"(a) : "l"(p));
    return a;
}
#define CP16(dst, src) \
    asm volatile("cp.async.ca.shared.global [%0], [%1], 16;" :: "r"(dst), "l"(src))
#define CP_COMMIT() asm volatile("cp.async.commit_group;" ::: "memory")
#define CP_WAIT1()  asm volatile("cp.async.wait_group 1;" ::: "memory")
#define CP_WAIT0()  asm volatile("cp.async.wait_group 0;" ::: "memory")

__device__ __forceinline__ void mma_tf32(float* d, const float* a, const float* b) {
    asm volatile(
        "mma.sync.aligned.m16n8k8.row.col.f32.tf32.tf32.f32 "
        "{%0,%1,%2,%3}, {%4,%5,%6,%7}, {%8,%9}, {%0,%1,%2,%3};"
        : "+f"(d[0]), "+f"(d[1]), "+f"(d[2]), "+f"(d[3])
        : "r"(__float_as_uint(a[0])), "r"(__float_as_uint(a[1])),
          "r"(__float_as_uint(a[2])), "r"(__float_as_uint(a[3])),
          "r"(__float_as_uint(b[0])), "r"(__float_as_uint(b[1])));
}
__device__ __forceinline__ void mma_bf16(float* d, const uint32_t* a, const uint32_t* b) {
    asm volatile(
        "mma.sync.aligned.m16n8k16.row.col.f32.bf16.bf16.f32 "
        "{%0,%1,%2,%3}, {%4,%5,%6,%7}, {%8,%9}, {%0,%1,%2,%3};"
        : "+f"(d[0]), "+f"(d[1]), "+f"(d[2]), "+f"(d[3])
        : "r"(a[0]), "r"(a[1]), "r"(a[2]), "r"(a[3]), "r"(b[0]), "r"(b[1]));
}

// ---------------------------------------------------------------------------
// tf32 GEMM: C[M, Nfull] = A[M,K] @ B^T, B stored [Nfull, K] K-major.
// RA: round A fragments to tf32 in-register (A not pre-rounded).
// MODE 1: fp32 tf32r(relu(acc+bias));  MODE 2: raw fp32;
// MODE 5: bf16 relu(acc+bias) written TRANSPOSED per batch:
//         Cbf[((m>>12)*Nfull + n)*4096 + (m&4095)].
// ---------------------------------------------------------------------------
template <int NT, int MODE, bool RA>
__global__ __launch_bounds__(256) void gemm_tf32(
    const float* __restrict__ A, const float* __restrict__ Bm, float* __restrict__ C,
    int M, int Nfull, int K, const float* __restrict__ bias,
    long sA, long sB, long sC)
{
    constexpr int BK = 16, LDA = 20;
    constexpr int WN_WARPS = (NT >= 128) ? 4 : 2;
    constexpr int WM_WARPS = 8 / WN_WARPS;
    constexpr int WMT = 128 / WM_WARPS;
    constexpr int WNT = NT / WN_WARPS;
    constexpr int MF = WMT / 16, NF = WNT / 8;
    constexpr int ASZ = 128 * LDA, BUF = ASZ + NT * LDA;

    extern __shared__ float sm[];
    const int tid = threadIdx.x, wid = tid >> 5, lane = tid & 31;
    const int lr = lane >> 2, lc = lane & 3;
    const int bz = blockIdx.z;

    A  += (size_t)bz * sA;
    Bm += (size_t)bz * sB;
    float* Cb = C + (size_t)bz * sC;

    const int m0 = blockIdx.y * 128, n0 = blockIdx.x * NT;
    const int wm = wid % WM_WARPS, wn = wid / WM_WARPS;
    const uint32_t sbase = smem_u32(sm);

    float acc[MF][NF][4];
#pragma unroll
    for (int i = 0; i < MF; i++)
#pragma unroll
        for (int j = 0; j < NF; j++)
#pragma unroll
            for (int r = 0; r < 4; r++) acc[i][j][r] = 0.f;

    auto stage = [&](int k0, int buf) {
#pragma unroll
        for (int l = 0; l < 2; l++) {
            int idx = tid + l * 256;
            int r = idx >> 2, q = idx & 3;
            CP16(sbase + (uint32_t)(buf * BUF + r * LDA + q * 4) * 4,
                 A + (size_t)(m0 + r) * K + k0 + q * 4);
        }
#pragma unroll
        for (int l = 0; l < NT / 64; l++) {
            int idx = tid + l * 256;
            int r = idx >> 2, q = idx & 3;
            CP16(sbase + (uint32_t)(buf * BUF + ASZ + r * LDA + q * 4) * 4,
                 Bm + (size_t)(n0 + r) * K + k0 + q * 4);
        }
        CP_COMMIT();
    };

    const int T = K / BK;
    stage(0, 0);
    for (int t = 0; t < T; t++) {
        if (t + 1 < T) { stage((t + 1) * BK, (t + 1) & 1); CP_WAIT1(); }
        else            { CP_WAIT0(); }
        __syncthreads();

        const float* As = sm + (t & 1) * BUF;
        const float* Bs = As + ASZ;
#pragma unroll
        for (int ks = 0; ks < 2; ks++) {
            const int kk = ks * 8 + lc;
            float a[MF][4], b[NF][2];
#pragma unroll
            for (int mf = 0; mf < MF; mf++) {
                const int r0 = (wm * WMT + mf * 16 + lr) * LDA;
                a[mf][0] = As[r0 + kk];
                a[mf][1] = As[r0 + 8 * LDA + kk];
                a[mf][2] = As[r0 + kk + 4];
                a[mf][3] = As[r0 + 8 * LDA + kk + 4];
                if (RA) {
#pragma unroll
                    for (int r = 0; r < 4; r++) a[mf][r] = tf32r(a[mf][r]);
                }
            }
#pragma unroll
            for (int nf = 0; nf < NF; nf++) {
                const int r0 = (wn * WNT + nf * 8 + lr) * LDA;
                b[nf][0] = Bs[r0 + kk];
                b[nf][1] = Bs[r0 + kk + 4];
            }
#pragma unroll
            for (int mf = 0; mf < MF; mf++)
#pragma unroll
                for (int nf = 0; nf < NF; nf++)
                    mma_tf32(acc[mf][nf], a[mf], b[nf]);
        }
        __syncthreads();
    }

    const int mb = m0 + wm * WMT, nb = n0 + wn * WNT;
#pragma unroll
    for (int mf = 0; mf < MF; mf++) {
        const int gr0 = mb + mf * 16 + lr, gr1 = gr0 + 8;
#pragma unroll
        for (int nf = 0; nf < NF; nf++) {
            const int gc = nb + nf * 8 + 2 * lc;
            const float* d = acc[mf][nf];
            if (MODE == 1) {
                Cb[(size_t)gr0 * Nfull + gc]     = tf32r(fmaxf(d[0] + bias[gc], 0.f));
                Cb[(size_t)gr0 * Nfull + gc + 1] = tf32r(fmaxf(d[1] + bias[gc + 1], 0.f));
                Cb[(size_t)gr1 * Nfull + gc]     = tf32r(fmaxf(d[2] + bias[gc], 0.f));
                Cb[(size_t)gr1 * Nfull + gc + 1] = tf32r(fmaxf(d[3] + bias[gc + 1], 0.f));
            } else if (MODE == 2) {
                Cb[(size_t)gr0 * Nfull + gc]     = d[0];
                Cb[(size_t)gr0 * Nfull + gc + 1] = d[1];
                Cb[(size_t)gr1 * Nfull + gc]     = d[2];
                Cb[(size_t)gr1 * Nfull + gc + 1] = d[3];
            } else {  // MODE 5: bf16, transposed-per-batch
                __nv_bfloat16* Ct = (__nv_bfloat16*)C;   // sC unused; gr encodes batch
                float v0 = fmaxf(d[0] + bias[gc], 0.f);
                float v1 = fmaxf(d[1] + bias[gc + 1], 0.f);
                float v2 = fmaxf(d[2] + bias[gc], 0.f);
                float v3 = fmaxf(d[3] + bias[gc + 1], 0.f);
                size_t b0 = ((size_t)(gr0 >> 12) * Nfull);
                size_t b1 = ((size_t)(gr1 >> 12) * Nfull);
                Ct[(b0 + gc)     * 4096 + (gr0 & 4095)] = __float2bfloat16_rn(v0);
                Ct[(b0 + gc + 1) * 4096 + (gr0 & 4095)] = __float2bfloat16_rn(v1);
                Ct[(b1 + gc)     * 4096 + (gr1 & 4095)] = __float2bfloat16_rn(v2);
                Ct[(b1 + gc + 1) * 4096 + (gr1 & 4095)] = __float2bfloat16_rn(v3);
            }
        }
    }
}

// ---------------------------------------------------------------------------
// bf16 GEMM (final): out[M,F] = gamma[n]*( (p @ hT^T)[m,n] / rowsum[m] ) + V[m,n]
// p [M,K] bf16 row-major; hT [F,K] bf16 K-major. m16n8k16. BK=32 halfs.
// SMEM as uint32 bf16-pairs, row stride 20 pairs (same conflict-free pattern).
// ---------------------------------------------------------------------------
__global__ __launch_bounds__(256) void gemm_bf16_o(
    const __nv_bfloat16* __restrict__ A, const __nv_bfloat16* __restrict__ Bm,
    float* __restrict__ C, int M, int Nfull, int K,
    const float* __restrict__ gamma, const float* __restrict__ vres,
    const float* __restrict__ rowsum, long sA, long sB, long sC, long sV)
{
    constexpr int NT = 128, LDA = 20;                 // pairs
    constexpr int WMT = 64, WNT = 32, MF = 4, NF = 4; // 2x4 warp grid
    constexpr int ASZ = 128 * LDA, BUF = ASZ + NT * LDA;

    extern __shared__ uint32_t smu[];
    const int tid = threadIdx.x, wid = tid >> 5, lane = tid & 31;
    const int lr = lane >> 2, lc = lane & 3;
    const int bz = blockIdx.z;

    A  += (size_t)bz * sA;
    Bm += (size_t)bz * sB;
    float* Cb = C + (size_t)bz * sC;
    const float* vres_b = vres + (size_t)bz * sV;
    const float* rs_b   = rowsum + (size_t)bz * M;

    const int m0 = blockIdx.y * 128, n0 = blockIdx.x * NT;
    const int wm = wid & 1, wn = wid >> 1;
    const uint32_t sbase = smem_u32(smu);

    float acc[MF][NF][4];
#pragma unroll
    for (int i = 0; i < MF; i++)
#pragma unroll
        for (int j = 0; j < NF; j++)
#pragma unroll
            for (int r = 0; r < 4; r++) acc[i][j][r] = 0.f;

    auto stage = [&](int k0, int buf) {   // k0 in halfs, multiples of 32
#pragma unroll
        for (int l = 0; l < 2; l++) {     // A: 128 rows x 32 halfs (64B = 4 cp16)
            int idx = tid + l * 256;
            int r = idx >> 2, q = idx & 3;
            CP16(sbase + (uint32_t)(buf * BUF + r * LDA + q * 4) * 4,
                 A + (size_t)(m0 + r) * K + k0 + q * 8);
        }
#pragma unroll
        for (int l = 0; l < 2; l++) {     // B: 128 rows x 32 halfs
            int idx = tid + l * 256;
            int r = idx >> 2, q = idx & 3;
            CP16(sbase + (uint32_t)(buf * BUF + ASZ + r * LDA + q * 4) * 4,
                 Bm + (size_t)(n0 + r) * K + k0 + q * 8);
        }
        CP_COMMIT();
    };

    const int T = K / 32;
    stage(0, 0);
    for (int t = 0; t < T; t++) {
        if (t + 1 < T) { stage((t + 1) * 32, (t + 1) & 1); CP_WAIT1(); }
        else            { CP_WAIT0(); }
        __syncthreads();

        const uint32_t* As = smu + (t & 1) * BUF;
        const uint32_t* Bs = As + ASZ;
#pragma unroll
        for (int ks = 0; ks < 2; ks++) {      // two k16 steps per 32-half tile
            const int kk = ks * 8 + lc;       // pair index
            uint32_t a[MF][4], b[NF][2];
#pragma unroll
            for (int mf = 0; mf < MF; mf++) {
                const int r0 = (wm * WMT + mf * 16 + lr) * LDA;
                a[mf][0] = As[r0 + kk];
                a[mf][1] = As[r0 + 8 * LDA + kk];
                a[mf][2] = As[r0 + kk + 4];
                a[mf][3] = As[r0 + 8 * LDA + kk + 4];
            }
#pragma unroll
            for (int nf = 0; nf < NF; nf++) {
                const int r0 = (wn * WNT + nf * 8 + lr) * LDA;
                b[nf][0] = Bs[r0 + kk];
                b[nf][1] = Bs[r0 + kk + 4];
            }
#pragma unroll
            for (int mf = 0; mf < MF; mf++)
#pragma unroll
                for (int nf = 0; nf < NF; nf++)
                    mma_bf16(acc[mf][nf], a[mf], b[nf]);
        }
        __syncthreads();
    }

    const int mb = m0 + wm * WMT, nb = n0 + wn * WNT;
#pragma unroll
    for (int mf = 0; mf < MF; mf++) {
        const int gr0 = mb + mf * 16 + lr, gr1 = gr0 + 8;
        const float inv0 = 1.f / rs_b[gr0], inv1 = 1.f / rs_b[gr1];
#pragma unroll
        for (int nf = 0; nf < NF; nf++) {
            const int gc = nb + nf * 8 + 2 * lc;
            const float* d = acc[mf][nf];
            Cb[(size_t)gr0 * Nfull + gc] =
                fmaf(gamma[gc], d[0] * inv0, vres_b[(size_t)gr0 * Nfull + gc]);
            Cb[(size_t)gr0 * Nfull + gc + 1] =
                fmaf(gamma[gc + 1], d[1] * inv0, vres_b[(size_t)gr0 * Nfull + gc + 1]);
            Cb[(size_t)gr1 * Nfull + gc] =
                fmaf(gamma[gc], d[2] * inv1, vres_b[(size_t)gr1 * Nfull + gc]);
            Cb[(size_t)gr1 * Nfull + gc + 1] =
                fmaf(gamma[gc + 1], d[3] * inv1, vres_b[(size_t)gr1 * Nfull + gc + 1]);
        }
    }
}

// ---------------------------------------------------------------------------
// Weight transpose (tf32-rounded): out[c][r] = round(in[r][c]).
// ---------------------------------------------------------------------------
__global__ void transpose_k(const float* __restrict__ in, float* __restrict__ out,
                            int R, int Ccols)
{
    __shared__ float t[32][33];
    const int c0 = blockIdx.x * 32, r0 = blockIdx.y * 32;
    const int x = threadIdx.x, y = threadIdx.y;
#pragma unroll
    for (int i = 0; i < 32; i += 8)
        t[y + i][x] = in[(size_t)(r0 + y + i) * Ccols + c0 + x];
    __syncthreads();
#pragma unroll
    for (int i = 0; i < 32; i += 8)
        out[(size_t)(c0 + y + i) * R + r0 + x] = tf32r(t[x][y + i]);
}

// ---------------------------------------------------------------------------
// Row softmax: reads s fp32, writes p = bf16(e^(x-max)) + fp32 rowsum.
// ---------------------------------------------------------------------------
__global__ __launch_bounds__(256) void softmax_k(const float* __restrict__ s,
                                                 __nv_bfloat16* __restrict__ p,
                                                 float* __restrict__ rs)
{
    const int row = blockIdx.x;
    const float* sp = s + (size_t)row * N_;
    __nv_bfloat16* pp = p + (size_t)row * N_;
    __shared__ float buf[N_];
    __shared__ float red[256];
    const int tid = threadIdx.x;

    float m = -INFINITY;
    for (int i = tid; i < N_; i += 256) {
        float v = sp[i];
        buf[i] = v;
        m = fmaxf(m, v);
    }
    red[tid] = m;
    __syncthreads();
    for (int st = 128; st > 0; st >>= 1) {
        if (tid < st) red[tid] = fmaxf(red[tid], red[tid + st]);
        __syncthreads();
    }
    const float mall = red[0];
    __syncthreads();

    float sum = 0.f;
    for (int i = tid; i < N_; i += 256) {
        float e = __expf(buf[i] - mall);
        pp[i] = __float2bfloat16_rn(e);
        sum += e;
    }
    red[tid] = sum;
    __syncthreads();
    for (int st = 128; st > 0; st >>= 1) {
        if (tid < st) red[tid] += red[tid + st];
        __syncthreads();
    }
    if (tid == 0) rs[row] = red[0];
}

// ---------------------------------------------------------------------------
extern "C" void kernel_launch(void* const* d_in, const int* in_sizes, int n_in,
                              void* d_out, int out_size)
{
    const float* V  = (const float*)d_in[0];
    const float* Wf = (const float*)d_in[1];
    const float* bf = (const float*)d_in[2];
    const float* Wg = (const float*)d_in[3];
    const float* bg = (const float*)d_in[4];
    const float* Wh = (const float*)d_in[5];
    const float* bh = (const float*)d_in[6];
    const float* gm = (const float*)d_in[7];
    float* out = (float*)d_out;

    float *fP, *gP, *sP, *rsP, *wfT, *wgT, *whT;
    __nv_bfloat16 *hTP, *pP;
    cudaGetSymbolAddress((void**)&fP,  g_f);
    cudaGetSymbolAddress((void**)&gP,  g_g);
    cudaGetSymbolAddress((void**)&hTP, g_hT);
    cudaGetSymbolAddress((void**)&sP,  g_s);
    cudaGetSymbolAddress((void**)&pP,  g_p);
    cudaGetSymbolAddress((void**)&rsP, g_rs);
    cudaGetSymbolAddress((void**)&wfT, g_wfT);
    cudaGetSymbolAddress((void**)&wgT, g_wgT);
    cudaGetSymbolAddress((void**)&whT, g_whT);

    const int SM128 = 2 * (128 + 128) * 20 * 4;   // 40960 B
    const int SM64  = 2 * (128 + 64)  * 20 * 4;   // 30720 B
    dim3 blk(256);
    dim3 tb(32, 8);

    // Weights -> K-major [N, K], tf32-rounded
    transpose_k<<<dim3(C_ / 32, F_ / 32), tb>>>(Wf, wfT, F_, C_);
    transpose_k<<<dim3(C_ / 32, F_ / 32), tb>>>(Wg, wgT, F_, C_);
    transpose_k<<<dim3(F_ / 32, F_ / 32), tb>>>(Wh, whT, F_, F_);

    // Projections (A=V rounded in-register)
    gemm_tf32<64, 1, true><<<dim3(1, 128, 1), blk, SM64>>>(
        V, wfT, fP, M_TOT, C_, F_, bf, 0, 0, 0);
    gemm_tf32<64, 1, true><<<dim3(1, 128, 1), blk, SM64>>>(
        V, wgT, gP, M_TOT, C_, F_, bg, 0, 0, 0);
    // h: relu(V@Wh+bh) written directly as transposed bf16 hT[B][F][N]
    gemm_tf32<128, 5, true><<<dim3(4, 128, 1), blk, SM128>>>(
        V, whT, (float*)hTP, M_TOT, F_, F_, bh, 0, 0, 0);

    // scores = f @ g^T per batch (raw fp32)
    gemm_tf32<128, 2, false><<<dim3(32, 32, B_), blk, SM128>>>(
        fP, gP, sP, N_, N_, C_, nullptr,
        (long)N_ * C_, (long)N_ * C_, (long)N_ * N_);

    // softmax: p = bf16(exp), rowsum fp32
    softmax_k<<<M_TOT, blk>>>(sP, pP, rsP);

    // out = gamma * (p @ h / rowsum) + V  (bf16 tensor path)
    gemm_bf16_o<<<dim3(4, 32, B_), blk, SM128>>>(
        pP, hTP, out, N_, F_, N_, gm, V, rsP,
        (long)N_ * N_, (long)F_ * N_, (long)N_ * F_, (long)N_ * F_);
}

// round 9
// speedup vs baseline: 7.3853x; 1.2607x over previous
// R7: issue-efficiency round. Opt-in smem: BK=32 tf32 tiles (2-stage, 72KB),
// BK=64-half bf16 o-GEMM (3-stage, 108KB). Vectorized softmax (float4 in,
// packed bf16x2 out) and float2 epilogue stores. Math identical to R6.
#include <cuda_runtime.h>
#include <cuda_bf16.h>
#include <cstdint>
#include <math.h>

#define B_    4
#define N_    4096
#define F_    512
#define C_    64
#define M_TOT (B_ * N_)   // 16384

// ---------------- scratch (allocation-free) ----------------
__device__ float g_f[M_TOT * C_];                        //  4 MiB (tf32-rounded)
__device__ float g_g[M_TOT * C_];                        //  4 MiB (tf32-rounded)
__device__ __nv_bfloat16 g_hT[(size_t)M_TOT * F_];       // 16 MiB, [B][F][N] bf16
__device__ float g_s[(size_t)M_TOT * N_];                // 256 MiB scores fp32
__device__ __nv_bfloat16 g_p[(size_t)M_TOT * N_];        // 128 MiB exp(bf16)
__device__ float g_rs[M_TOT];
__device__ float g_wfT[C_ * F_];
__device__ float g_wgT[C_ * F_];
__device__ float g_whT[F_ * F_];

// ---------------- helpers ----------------
__device__ __forceinline__ float tf32r(float x) {
    uint32_t u;
    asm("cvt.rna.tf32.f32 %0, %1;" : "=r"(u) : "f"(x));
    return __uint_as_float(u);
}
__device__ __forceinline__ uint32_t smem_u32(const void* p) {
    uint32_t a;
    asm("{ .reg .u64 t; cvta.to.shared.u64 t, %1; cvt.u32.u64 %0, t; }" : "=r"(a) : "l"(p));
    return a;
}
#define CP16(dst, src) \
    asm volatile("cp.async.ca.shared.global [%0], [%1], 16;" :: "r"(dst), "l"(src))
#define CP_COMMIT() asm volatile("cp.async.commit_group;" ::: "memory")
#define CP_WAIT2()  asm volatile("cp.async.wait_group 2;" ::: "memory")
#define CP_WAIT1()  asm volatile("cp.async.wait_group 1;" ::: "memory")
#define CP_WAIT0()  asm volatile("cp.async.wait_group 0;" ::: "memory")

__device__ __forceinline__ void mma_tf32(float* d, const float* a, const float* b) {
    asm volatile(
        "mma.sync.aligned.m16n8k8.row.col.f32.tf32.tf32.f32 "
        "{%0,%1,%2,%3}, {%4,%5,%6,%7}, {%8,%9}, {%0,%1,%2,%3};"
        : "+f"(d[0]), "+f"(d[1]), "+f"(d[2]), "+f"(d[3])
        : "r"(__float_as_uint(a[0])), "r"(__float_as_uint(a[1])),
          "r"(__float_as_uint(a[2])), "r"(__float_as_uint(a[3])),
          "r"(__float_as_uint(b[0])), "r"(__float_as_uint(b[1])));
}
__device__ __forceinline__ void mma_bf16(float* d, const uint32_t* a, const uint32_t* b) {
    asm volatile(
        "mma.sync.aligned.m16n8k16.row.col.f32.bf16.bf16.f32 "
        "{%0,%1,%2,%3}, {%4,%5,%6,%7}, {%8,%9}, {%0,%1,%2,%3};"
        : "+f"(d[0]), "+f"(d[1]), "+f"(d[2]), "+f"(d[3])
        : "r"(a[0]), "r"(a[1]), "r"(a[2]), "r"(a[3]), "r"(b[0]), "r"(b[1]));
}

// ---------------------------------------------------------------------------
// tf32 GEMM: C[M, Nfull] = A[M,K] @ B^T, B stored [Nfull, K] K-major.
// BK=32, LDA=36 floats, 2-stage cp.async. RA: round A frags to tf32 in-reg.
// MODE 1: fp32 tf32r(relu(acc+bias));  MODE 2: raw fp32 (float2 stores);
// MODE 5: bf16 relu(acc+bias) written transposed per batch.
// ---------------------------------------------------------------------------
template <int NT, int MODE, bool RA>
__global__ __launch_bounds__(256) void gemm_tf32(
    const float* __restrict__ A, const float* __restrict__ Bm, float* __restrict__ C,
    int M, int Nfull, int K, const float* __restrict__ bias,
    long sA, long sB, long sC)
{
    constexpr int BK = 32, LDA = 36;
    constexpr int WN_WARPS = (NT >= 128) ? 4 : 2;
    constexpr int WM_WARPS = 8 / WN_WARPS;
    constexpr int WMT = 128 / WM_WARPS;
    constexpr int WNT = NT / WN_WARPS;
    constexpr int MF = WMT / 16, NF = WNT / 8;
    constexpr int ASZ = 128 * LDA, BUF = ASZ + NT * LDA;
    constexpr int LB = NT / 32;                       // B stage iters

    extern __shared__ float sm[];
    const int tid = threadIdx.x, wid = tid >> 5, lane = tid & 31;
    const int lr = lane >> 2, lc = lane & 3;
    const int bz = blockIdx.z;

    A  += (size_t)bz * sA;
    Bm += (size_t)bz * sB;
    float* Cb = C + (size_t)bz * sC;

    const int m0 = blockIdx.y * 128, n0 = blockIdx.x * NT;
    const int wm = wid % WM_WARPS, wn = wid / WM_WARPS;
    const uint32_t sbase = smem_u32(sm);

    float acc[MF][NF][4];
#pragma unroll
    for (int i = 0; i < MF; i++)
#pragma unroll
        for (int j = 0; j < NF; j++)
#pragma unroll
            for (int r = 0; r < 4; r++) acc[i][j][r] = 0.f;

    auto stage = [&](int k0, int buf) {
#pragma unroll
        for (int l = 0; l < 4; l++) {                 // A: 128 rows x 32 floats
            int idx = tid + l * 256;
            int r = idx >> 3, q = idx & 7;
            CP16(sbase + (uint32_t)(buf * BUF + r * LDA + q * 4) * 4,
                 A + (size_t)(m0 + r) * K + k0 + q * 4);
        }
#pragma unroll
        for (int l = 0; l < LB; l++) {                // B: NT rows x 32 floats
            int idx = tid + l * 256;
            int r = idx >> 3, q = idx & 7;
            CP16(sbase + (uint32_t)(buf * BUF + ASZ + r * LDA + q * 4) * 4,
                 Bm + (size_t)(n0 + r) * K + k0 + q * 4);
        }
        CP_COMMIT();
    };

    const int T = K / BK;
    stage(0, 0);
    for (int t = 0; t < T; t++) {
        if (t + 1 < T) { stage((t + 1) * BK, (t + 1) & 1); CP_WAIT1(); }
        else            { CP_WAIT0(); }
        __syncthreads();

        const float* As = sm + (t & 1) * BUF;
        const float* Bs = As + ASZ;
#pragma unroll
        for (int ks = 0; ks < BK / 8; ks++) {
            const int kk = ks * 8 + lc;
            float a[MF][4], b[NF][2];
#pragma unroll
            for (int mf = 0; mf < MF; mf++) {
                const int r0 = (wm * WMT + mf * 16 + lr) * LDA;
                a[mf][0] = As[r0 + kk];
                a[mf][1] = As[r0 + 8 * LDA + kk];
                a[mf][2] = As[r0 + kk + 4];
                a[mf][3] = As[r0 + 8 * LDA + kk + 4];
                if (RA) {
#pragma unroll
                    for (int r = 0; r < 4; r++) a[mf][r] = tf32r(a[mf][r]);
                }
            }
#pragma unroll
            for (int nf = 0; nf < NF; nf++) {
                const int r0 = (wn * WNT + nf * 8 + lr) * LDA;
                b[nf][0] = Bs[r0 + kk];
                b[nf][1] = Bs[r0 + kk + 4];
            }
#pragma unroll
            for (int mf = 0; mf < MF; mf++)
#pragma unroll
                for (int nf = 0; nf < NF; nf++)
                    mma_tf32(acc[mf][nf], a[mf], b[nf]);
        }
        __syncthreads();
    }

    const int mb = m0 + wm * WMT, nb = n0 + wn * WNT;
#pragma unroll
    for (int mf = 0; mf < MF; mf++) {
        const int gr0 = mb + mf * 16 + lr, gr1 = gr0 + 8;
#pragma unroll
        for (int nf = 0; nf < NF; nf++) {
            const int gc = nb + nf * 8 + 2 * lc;
            const float* d = acc[mf][nf];
            if (MODE == 1) {
                Cb[(size_t)gr0 * Nfull + gc]     = tf32r(fmaxf(d[0] + bias[gc], 0.f));
                Cb[(size_t)gr0 * Nfull + gc + 1] = tf32r(fmaxf(d[1] + bias[gc + 1], 0.f));
                Cb[(size_t)gr1 * Nfull + gc]     = tf32r(fmaxf(d[2] + bias[gc], 0.f));
                Cb[(size_t)gr1 * Nfull + gc + 1] = tf32r(fmaxf(d[3] + bias[gc + 1], 0.f));
            } else if (MODE == 2) {
                *reinterpret_cast<float2*>(&Cb[(size_t)gr0 * Nfull + gc]) =
                    make_float2(d[0], d[1]);
                *reinterpret_cast<float2*>(&Cb[(size_t)gr1 * Nfull + gc]) =
                    make_float2(d[2], d[3]);
            } else {  // MODE 5: bf16, transposed per batch
                __nv_bfloat16* Ct = (__nv_bfloat16*)C;
                float v0 = fmaxf(d[0] + bias[gc], 0.f);
                float v1 = fmaxf(d[1] + bias[gc + 1], 0.f);
                float v2 = fmaxf(d[2] + bias[gc], 0.f);
                float v3 = fmaxf(d[3] + bias[gc + 1], 0.f);
                size_t b0 = ((size_t)(gr0 >> 12) * Nfull);
                size_t b1 = ((size_t)(gr1 >> 12) * Nfull);
                Ct[(b0 + gc)     * 4096 + (gr0 & 4095)] = __float2bfloat16_rn(v0);
                Ct[(b0 + gc + 1) * 4096 + (gr0 & 4095)] = __float2bfloat16_rn(v1);
                Ct[(b1 + gc)     * 4096 + (gr1 & 4095)] = __float2bfloat16_rn(v2);
                Ct[(b1 + gc + 1) * 4096 + (gr1 & 4095)] = __float2bfloat16_rn(v3);
            }
        }
    }
}

// ---------------------------------------------------------------------------
// bf16 GEMM (final): out = gamma[n]*((p @ hT^T)/rowsum[m]) + V.
// BK=64 halfs (32 pairs, LDA=36 uint32), 3-stage cp.async pipeline.
// ---------------------------------------------------------------------------
__global__ __launch_bounds__(256) void gemm_bf16_o(
    const __nv_bfloat16* __restrict__ A, const __nv_bfloat16* __restrict__ Bm,
    float* __restrict__ C, int M, int Nfull, int K,
    const float* __restrict__ gamma, const float* __restrict__ vres,
    const float* __restrict__ rowsum, long sA, long sB, long sC, long sV)
{
    constexpr int NT = 128, LDA = 36;                 // uint32 pairs per row
    constexpr int BKH = 64;                           // halfs per tile
    constexpr int WMT = 64, WNT = 32, MF = 4, NF = 4;
    constexpr int ASZ = 128 * LDA, BUF = ASZ + NT * LDA;

    extern __shared__ uint32_t smu[];
    const int tid = threadIdx.x, wid = tid >> 5, lane = tid & 31;
    const int lr = lane >> 2, lc = lane & 3;
    const int bz = blockIdx.z;

    A  += (size_t)bz * sA;
    Bm += (size_t)bz * sB;
    float* Cb = C + (size_t)bz * sC;
    const float* vres_b = vres + (size_t)bz * sV;
    const float* rs_b   = rowsum + (size_t)bz * M;

    const int m0 = blockIdx.y * 128, n0 = blockIdx.x * NT;
    const int wm = wid & 1, wn = wid >> 1;
    const uint32_t sbase = smem_u32(smu);

    float acc[MF][NF][4];
#pragma unroll
    for (int i = 0; i < MF; i++)
#pragma unroll
        for (int j = 0; j < NF; j++)
#pragma unroll
            for (int r = 0; r < 4; r++) acc[i][j][r] = 0.f;

    auto stage = [&](int k0, int buf) {   // k0 in halfs
#pragma unroll
        for (int l = 0; l < 4; l++) {     // A: 128 rows x 64 halfs
            int idx = tid + l * 256;
            int r = idx >> 3, q = idx & 7;
            CP16(sbase + (uint32_t)(buf * BUF + r * LDA + q * 4) * 4,
                 A + (size_t)(m0 + r) * K + k0 + q * 8);
        }
#pragma unroll
        for (int l = 0; l < 4; l++) {     // B: 128 rows x 64 halfs
            int idx = tid + l * 256;
            int r = idx >> 3, q = idx & 7;
            CP16(sbase + (uint32_t)(buf * BUF + ASZ + r * LDA + q * 4) * 4,
                 Bm + (size_t)(n0 + r) * K + k0 + q * 8);
        }
        CP_COMMIT();
    };

    const int T = K / BKH;                // 64
    stage(0, 0);
    stage(BKH, 1);
    for (int t = 0; t < T; t++) {
        if (t + 2 < T) { stage((t + 2) * BKH, (t + 2) % 3); CP_WAIT2(); }
        else if (t + 1 < T) { CP_WAIT1(); }
        else { CP_WAIT0(); }
        __syncthreads();

        const uint32_t* As = smu + (t % 3) * BUF;
        const uint32_t* Bs = As + ASZ;
#pragma unroll
        for (int ks = 0; ks < 4; ks++) {      // 4 k16 steps per tile
            const int kk = ks * 8 + lc;       // pair index
            uint32_t a[MF][4], b[NF][2];
#pragma unroll
            for (int mf = 0; mf < MF; mf++) {
                const int r0 = (wm * WMT + mf * 16 + lr) * LDA;
                a[mf][0] = As[r0 + kk];
                a[mf][1] = As[r0 + 8 * LDA + kk];
                a[mf][2] = As[r0 + kk + 4];
                a[mf][3] = As[r0 + 8 * LDA + kk + 4];
            }
#pragma unroll
            for (int nf = 0; nf < NF; nf++) {
                const int r0 = (wn * WNT + nf * 8 + lr) * LDA;
                b[nf][0] = Bs[r0 + kk];
                b[nf][1] = Bs[r0 + kk + 4];
            }
#pragma unroll
            for (int mf = 0; mf < MF; mf++)
#pragma unroll
                for (int nf = 0; nf < NF; nf++)
                    mma_bf16(acc[mf][nf], a[mf], b[nf]);
        }
        __syncthreads();
    }

    const int mb = m0 + wm * WMT, nb = n0 + wn * WNT;
#pragma unroll
    for (int mf = 0; mf < MF; mf++) {
        const int gr0 = mb + mf * 16 + lr, gr1 = gr0 + 8;
        const float inv0 = 1.f / rs_b[gr0], inv1 = 1.f / rs_b[gr1];
#pragma unroll
        for (int nf = 0; nf < NF; nf++) {
            const int gc = nb + nf * 8 + 2 * lc;
            const float* d = acc[mf][nf];
            float2 vr0 = *reinterpret_cast<const float2*>(&vres_b[(size_t)gr0 * Nfull + gc]);
            float2 vr1 = *reinterpret_cast<const float2*>(&vres_b[(size_t)gr1 * Nfull + gc]);
            float2 gg  = *reinterpret_cast<const float2*>(&gamma[gc]);
            *reinterpret_cast<float2*>(&Cb[(size_t)gr0 * Nfull + gc]) =
                make_float2(fmaf(gg.x, d[0] * inv0, vr0.x), fmaf(gg.y, d[1] * inv0, vr0.y));
            *reinterpret_cast<float2*>(&Cb[(size_t)gr1 * Nfull + gc]) =
                make_float2(fmaf(gg.x, d[2] * inv1, vr1.x), fmaf(gg.y, d[3] * inv1, vr1.y));
        }
    }
}

// ---------------------------------------------------------------------------
// Weight transpose (tf32-rounded): out[c][r] = round(in[r][c]).
// ---------------------------------------------------------------------------
__global__ void transpose_k(const float* __restrict__ in, float* __restrict__ out,
                            int R, int Ccols)
{
    __shared__ float t[32][33];
    const int c0 = blockIdx.x * 32, r0 = blockIdx.y * 32;
    const int x = threadIdx.x, y = threadIdx.y;
#pragma unroll
    for (int i = 0; i < 32; i += 8)
        t[y + i][x] = in[(size_t)(r0 + y + i) * Ccols + c0 + x];
    __syncthreads();
#pragma unroll
    for (int i = 0; i < 32; i += 8)
        out[(size_t)(c0 + y + i) * R + r0 + x] = tf32r(t[x][y + i]);
}

// ---------------------------------------------------------------------------
// Row softmax: reads s fp32 (float4), writes p = bf16(e^(x-max)) packed uint2,
// plus fp32 rowsum. One 4096-wide row per block, 256 threads.
// ---------------------------------------------------------------------------
__global__ __launch_bounds__(256) void softmax_k(const float4* __restrict__ s,
                                                 uint2* __restrict__ p,
                                                 float* __restrict__ rs)
{
    const int row = blockIdx.x;
    const float4* sp = s + (size_t)row * (N_ / 4);
    uint2* pp = p + (size_t)row * (N_ / 4);
    __shared__ float4 buf[N_ / 4];
    __shared__ float red[256];
    const int tid = threadIdx.x;

    float m = -INFINITY;
#pragma unroll
    for (int l = 0; l < 4; l++) {
        int i = tid + l * 256;
        float4 v = sp[i];
        buf[i] = v;
        m = fmaxf(m, fmaxf(fmaxf(v.x, v.y), fmaxf(v.z, v.w)));
    }
    red[tid] = m;
    __syncthreads();
    for (int st = 128; st > 0; st >>= 1) {
        if (tid < st) red[tid] = fmaxf(red[tid], red[tid + st]);
        __syncthreads();
    }
    const float mall = red[0];
    __syncthreads();

    float sum = 0.f;
#pragma unroll
    for (int l = 0; l < 4; l++) {
        int i = tid + l * 256;
        float4 v = buf[i];
        float e0 = __expf(v.x - mall), e1 = __expf(v.y - mall);
        float e2 = __expf(v.z - mall), e3 = __expf(v.w - mall);
        __nv_bfloat162 h0 = __floats2bfloat162_rn(e0, e1);
        __nv_bfloat162 h1 = __floats2bfloat162_rn(e2, e3);
        uint2 w;
        w.x = *reinterpret_cast<uint32_t*>(&h0);
        w.y = *reinterpret_cast<uint32_t*>(&h1);
        pp[i] = w;
        sum += (e0 + e1) + (e2 + e3);
    }
    red[tid] = sum;
    __syncthreads();
    for (int st = 128; st > 0; st >>= 1) {
        if (tid < st) red[tid] += red[tid + st];
        __syncthreads();
    }
    if (tid == 0) rs[row] = red[0];
}

// ---------------------------------------------------------------------------
extern "C" void kernel_launch(void* const* d_in, const int* in_sizes, int n_in,
                              void* d_out, int out_size)
{
    const float* V  = (const float*)d_in[0];
    const float* Wf = (const float*)d_in[1];
    const float* bf = (const float*)d_in[2];
    const float* Wg = (const float*)d_in[3];
    const float* bg = (const float*)d_in[4];
    const float* Wh = (const float*)d_in[5];
    const float* bh = (const float*)d_in[6];
    const float* gm = (const float*)d_in[7];
    float* out = (float*)d_out;

    float *fP, *gP, *sP, *rsP, *wfT, *wgT, *whT;
    __nv_bfloat16 *hTP, *pP;
    cudaGetSymbolAddress((void**)&fP,  g_f);
    cudaGetSymbolAddress((void**)&gP,  g_g);
    cudaGetSymbolAddress((void**)&hTP, g_hT);
    cudaGetSymbolAddress((void**)&sP,  g_s);
    cudaGetSymbolAddress((void**)&pP,  g_p);
    cudaGetSymbolAddress((void**)&rsP, g_rs);
    cudaGetSymbolAddress((void**)&wfT, g_wfT);
    cudaGetSymbolAddress((void**)&wgT, g_wgT);
    cudaGetSymbolAddress((void**)&whT, g_whT);

    const int SM_TF128 = 2 * (128 + 128) * 36 * 4;   // 73728 B
    const int SM_TF64  = 2 * (128 + 64)  * 36 * 4;   // 55296 B
    const int SM_BF    = 3 * (128 + 128) * 36 * 4;   // 110592 B

    // Opt-in to >48KB dynamic smem (idempotent; set on pre-capture call too)
    cudaFuncSetAttribute(gemm_tf32<64, 1, true>,
                         cudaFuncAttributeMaxDynamicSharedMemorySize, SM_TF64);
    cudaFuncSetAttribute(gemm_tf32<128, 5, true>,
                         cudaFuncAttributeMaxDynamicSharedMemorySize, SM_TF128);
    cudaFuncSetAttribute(gemm_tf32<128, 2, false>,
                         cudaFuncAttributeMaxDynamicSharedMemorySize, SM_TF128);
    cudaFuncSetAttribute(gemm_bf16_o,
                         cudaFuncAttributeMaxDynamicSharedMemorySize, SM_BF);

    dim3 blk(256);
    dim3 tb(32, 8);

    // Weights -> K-major [N, K], tf32-rounded
    transpose_k<<<dim3(C_ / 32, F_ / 32), tb>>>(Wf, wfT, F_, C_);
    transpose_k<<<dim3(C_ / 32, F_ / 32), tb>>>(Wg, wgT, F_, C_);
    transpose_k<<<dim3(F_ / 32, F_ / 32), tb>>>(Wh, whT, F_, F_);

    // Projections (A=V rounded in-register)
    gemm_tf32<64, 1, true><<<dim3(1, 128, 1), blk, SM_TF64>>>(
        V, wfT, fP, M_TOT, C_, F_, bf, 0, 0, 0);
    gemm_tf32<64, 1, true><<<dim3(1, 128, 1), blk, SM_TF64>>>(
        V, wgT, gP, M_TOT, C_, F_, bg, 0, 0, 0);
    // h: relu(V@Wh+bh) written directly as transposed bf16 hT[B][F][N]
    gemm_tf32<128, 5, true><<<dim3(4, 128, 1), blk, SM_TF128>>>(
        V, whT, (float*)hTP, M_TOT, F_, F_, bh, 0, 0, 0);

    // scores = f @ g^T per batch (raw fp32, T=2 K-tiles)
    gemm_tf32<128, 2, false><<<dim3(32, 32, B_), blk, SM_TF128>>>(
        fP, gP, sP, N_, N_, C_, nullptr,
        (long)N_ * C_, (long)N_ * C_, (long)N_ * N_);

    // softmax: p = bf16(exp), rowsum fp32
    softmax_k<<<M_TOT, blk>>>((const float4*)sP, (uint2*)pP, rsP);

    // out = gamma * (p @ h / rowsum) + V  (bf16, 3-stage pipeline)
    gemm_bf16_o<<<dim3(4, 32, B_), blk, SM_BF>>>(
        pP, hTP, out, N_, F_, N_, gm, V, rsP,
        (long)N_ * N_, (long)F_ * N_, (long)N_ * F_, (long)N_ * F_);
}

// round 10
// speedup vs baseline: 8.2878x; 1.1222x over previous
// R9: kill the s fp32 buffer + softmax kernel. Cauchy-Schwarz row bound
// M_i = ||f_i||*max||g|| (valid since f,g >= 0) lets the scores epilogue emit
// p = bf16(exp(s-M_i)) directly + deterministic partial rowsums. f+g fused
// into one GEMM with stacked weights. o-GEMM unchanged from R7.
#include <cuda_runtime.h>
#include <cuda_bf16.h>
#include <cstdint>
#include <math.h>

#define B_    4
#define N_    4096
#define F_    512
#define C_    64
#define M_TOT (B_ * N_)   // 16384

// ---------------- scratch (allocation-free) ----------------
__device__ float g_fg[(size_t)M_TOT * 128];              //  8 MiB [f|g] tf32
__device__ __nv_bfloat16 g_hT[(size_t)M_TOT * F_];       // 16 MiB, [B][F][N] bf16
__device__ __nv_bfloat16 g_p[(size_t)M_TOT * N_];        // 128 MiB exp(bf16)
__device__ float g_part[(size_t)32 * M_TOT];             //  2 MiB partial rowsums
__device__ float g_rs[M_TOT];
__device__ float g_normf[M_TOT];
__device__ int   g_maxg[B_];
__device__ float g_bfg[128];
__device__ float g_wfgT[128 * F_];                       // stacked [WfT; WgT]
__device__ float g_whT[F_ * F_];

// ---------------- helpers ----------------
__device__ __forceinline__ float tf32r(float x) {
    uint32_t u;
    asm("cvt.rna.tf32.f32 %0, %1;" : "=r"(u) : "f"(x));
    return __uint_as_float(u);
}
__device__ __forceinline__ uint32_t smem_u32(const void* p) {
    uint32_t a;
    asm("{ .reg .u64 t; cvta.to.shared.u64 t, %1; cvt.u32.u64 %0, t; }" : "=r"(a) : "l"(p));
    return a;
}
#define CP16(dst, src) \
    asm volatile("cp.async.ca.shared.global [%0], [%1], 16;" :: "r"(dst), "l"(src))
#define CP_COMMIT() asm volatile("cp.async.commit_group;" ::: "memory")
#define CP_WAIT2()  asm volatile("cp.async.wait_group 2;" ::: "memory")
#define CP_WAIT1()  asm volatile("cp.async.wait_group 1;" ::: "memory")
#define CP_WAIT0()  asm volatile("cp.async.wait_group 0;" ::: "memory")

__device__ __forceinline__ void mma_tf32(float* d, const float* a, const float* b) {
    asm volatile(
        "mma.sync.aligned.m16n8k8.row.col.f32.tf32.tf32.f32 "
        "{%0,%1,%2,%3}, {%4,%5,%6,%7}, {%8,%9}, {%0,%1,%2,%3};"
        : "+f"(d[0]), "+f"(d[1]), "+f"(d[2]), "+f"(d[3])
        : "r"(__float_as_uint(a[0])), "r"(__float_as_uint(a[1])),
          "r"(__float_as_uint(a[2])), "r"(__float_as_uint(a[3])),
          "r"(__float_as_uint(b[0])), "r"(__float_as_uint(b[1])));
}
__device__ __forceinline__ void mma_bf16(float* d, const uint32_t* a, const uint32_t* b) {
    asm volatile(
        "mma.sync.aligned.m16n8k16.row.col.f32.bf16.bf16.f32 "
        "{%0,%1,%2,%3}, {%4,%5,%6,%7}, {%8,%9}, {%0,%1,%2,%3};"
        : "+f"(d[0]), "+f"(d[1]), "+f"(d[2]), "+f"(d[3])
        : "r"(a[0]), "r"(a[1]), "r"(a[2]), "r"(a[3]), "r"(b[0]), "r"(b[1]));
}

// ---------------------------------------------------------------------------
// tf32 GEMM: C[M, Nfull] = A[M,K] @ B^T, B stored [Nfull rows, K] with row
// stride ldB; A row stride ldA. BK=32, LDA_S=36 floats, 2-stage cp.async.
// RA: round A frags to tf32 in-register.
// MODE 1: fp32 tf32r(relu(acc+bias)) -> C.
// MODE 5: bf16 relu(acc+bias) written transposed per batch (h path).
// MODE 6: p = bf16(exp(acc - normf[row]*maxg[bz])) -> C (bf16, batch stride sC
//         in halfs); deterministic partial rowsums -> partial[blockIdx.x][row].
// ---------------------------------------------------------------------------
template <int NT, int MODE, bool RA>
__global__ __launch_bounds__(256) void gemm_tf32(
    const float* __restrict__ A, const float* __restrict__ Bm, float* __restrict__ C,
    int M, int Nfull, int K, int ldA, int ldB,
    const float* __restrict__ bias,
    const float* __restrict__ normf, const int* __restrict__ maxg,
    float* __restrict__ partial,
    long sA, long sB, long sC)
{
    constexpr int BK = 32, LDS = 36;
    constexpr int WN_WARPS = 4, WM_WARPS = 2;
    constexpr int WMT = 64;
    constexpr int WNT = NT / WN_WARPS;
    constexpr int MF = 4, NF = WNT / 8;
    constexpr int ASZ = 128 * LDS, BUF = ASZ + NT * LDS;
    constexpr int LB = NT / 32;

    extern __shared__ float sm[];
    const int tid = threadIdx.x, wid = tid >> 5, lane = tid & 31;
    const int lr = lane >> 2, lc = lane & 3;
    const int bz = blockIdx.z;

    A  += (size_t)bz * sA;
    Bm += (size_t)bz * sB;
    float* Cb = C;
    if (MODE == 1) Cb = C + (size_t)bz * sC;

    const int m0 = blockIdx.y * 128, n0 = blockIdx.x * NT;
    const int wm = wid % WM_WARPS, wn = wid / WM_WARPS;
    const uint32_t sbase = smem_u32(sm);

    float acc[MF][NF][4];
#pragma unroll
    for (int i = 0; i < MF; i++)
#pragma unroll
        for (int j = 0; j < NF; j++)
#pragma unroll
            for (int r = 0; r < 4; r++) acc[i][j][r] = 0.f;

    auto stage = [&](int k0, int buf) {
#pragma unroll
        for (int l = 0; l < 4; l++) {                 // A: 128 rows x 32 floats
            int idx = tid + l * 256;
            int r = idx >> 3, q = idx & 7;
            CP16(sbase + (uint32_t)(buf * BUF + r * LDS + q * 4) * 4,
                 A + (size_t)(m0 + r) * ldA + k0 + q * 4);
        }
#pragma unroll
        for (int l = 0; l < LB; l++) {                // B: NT rows x 32 floats
            int idx = tid + l * 256;
            int r = idx >> 3, q = idx & 7;
            CP16(sbase + (uint32_t)(buf * BUF + ASZ + r * LDS + q * 4) * 4,
                 Bm + (size_t)(n0 + r) * ldB + k0 + q * 4);
        }
        CP_COMMIT();
    };

    const int T = K / BK;
    stage(0, 0);
    for (int t = 0; t < T; t++) {
        if (t + 1 < T) { stage((t + 1) * BK, (t + 1) & 1); CP_WAIT1(); }
        else            { CP_WAIT0(); }
        __syncthreads();

        const float* As = sm + (t & 1) * BUF;
        const float* Bs = As + ASZ;
#pragma unroll
        for (int ks = 0; ks < BK / 8; ks++) {
            const int kk = ks * 8 + lc;
            float a[MF][4], b[NF][2];
#pragma unroll
            for (int mf = 0; mf < MF; mf++) {
                const int r0 = (wm * WMT + mf * 16 + lr) * LDS;
                a[mf][0] = As[r0 + kk];
                a[mf][1] = As[r0 + 8 * LDS + kk];
                a[mf][2] = As[r0 + kk + 4];
                a[mf][3] = As[r0 + 8 * LDS + kk + 4];
                if (RA) {
#pragma unroll
                    for (int r = 0; r < 4; r++) a[mf][r] = tf32r(a[mf][r]);
                }
            }
#pragma unroll
            for (int nf = 0; nf < NF; nf++) {
                const int r0 = (wn * WNT + nf * 8 + lr) * LDS;
                b[nf][0] = Bs[r0 + kk];
                b[nf][1] = Bs[r0 + kk + 4];
            }
#pragma unroll
            for (int mf = 0; mf < MF; mf++)
#pragma unroll
                for (int nf = 0; nf < NF; nf++)
                    mma_tf32(acc[mf][nf], a[mf], b[nf]);
        }
        __syncthreads();
    }

    const int mb = m0 + wm * WMT, nb = n0 + wn * WNT;

    if (MODE == 1) {
#pragma unroll
        for (int mf = 0; mf < MF; mf++) {
            const int gr0 = mb + mf * 16 + lr, gr1 = gr0 + 8;
#pragma unroll
            for (int nf = 0; nf < NF; nf++) {
                const int gc = nb + nf * 8 + 2 * lc;
                const float* d = acc[mf][nf];
                *reinterpret_cast<float2*>(&Cb[(size_t)gr0 * Nfull + gc]) =
                    make_float2(tf32r(fmaxf(d[0] + bias[gc], 0.f)),
                                tf32r(fmaxf(d[1] + bias[gc + 1], 0.f)));
                *reinterpret_cast<float2*>(&Cb[(size_t)gr1 * Nfull + gc]) =
                    make_float2(tf32r(fmaxf(d[2] + bias[gc], 0.f)),
                                tf32r(fmaxf(d[3] + bias[gc + 1], 0.f)));
            }
        }
    } else if (MODE == 5) {
        __nv_bfloat16* Ct = (__nv_bfloat16*)C;
#pragma unroll
        for (int mf = 0; mf < MF; mf++) {
            const int gr0 = mb + mf * 16 + lr, gr1 = gr0 + 8;
#pragma unroll
            for (int nf = 0; nf < NF; nf++) {
                const int gc = nb + nf * 8 + 2 * lc;
                const float* d = acc[mf][nf];
                float v0 = fmaxf(d[0] + bias[gc], 0.f);
                float v1 = fmaxf(d[1] + bias[gc + 1], 0.f);
                float v2 = fmaxf(d[2] + bias[gc], 0.f);
                float v3 = fmaxf(d[3] + bias[gc + 1], 0.f);
                size_t b0 = ((size_t)(gr0 >> 12) * Nfull);
                size_t b1 = ((size_t)(gr1 >> 12) * Nfull);
                Ct[(b0 + gc)     * 4096 + (gr0 & 4095)] = __float2bfloat16_rn(v0);
                Ct[(b0 + gc + 1) * 4096 + (gr0 & 4095)] = __float2bfloat16_rn(v1);
                Ct[(b1 + gc)     * 4096 + (gr1 & 4095)] = __float2bfloat16_rn(v2);
                Ct[(b1 + gc + 1) * 4096 + (gr1 & 4095)] = __float2bfloat16_rn(v3);
            }
        }
    } else {  // MODE 6
        __nv_bfloat16* Pb = (__nv_bfloat16*)C + (size_t)bz * sC;
        float* spart = sm;                    // reuse smem (all reads done)
        const float Mg = __int_as_float(maxg[bz]);
        const int grow_base = bz * 4096;
#pragma unroll
        for (int mf = 0; mf < MF; mf++) {
            const int gr0 = mb + mf * 16 + lr, gr1 = gr0 + 8;
            const float M0 = normf[grow_base + gr0] * Mg;
            const float M1 = normf[grow_base + gr1] * Mg;
            float s0 = 0.f, s1 = 0.f;
#pragma unroll
            for (int nf = 0; nf < NF; nf++) {
                const int gc = nb + nf * 8 + 2 * lc;
                const float* d = acc[mf][nf];
                float e0 = __expf(d[0] - M0), e1 = __expf(d[1] - M0);
                float e2 = __expf(d[2] - M1), e3 = __expf(d[3] - M1);
                __nv_bfloat162 h0 = __floats2bfloat162_rn(e0, e1);
                __nv_bfloat162 h1 = __floats2bfloat162_rn(e2, e3);
                *reinterpret_cast<uint32_t*>(&Pb[(size_t)gr0 * Nfull + gc]) =
                    *reinterpret_cast<uint32_t*>(&h0);
                *reinterpret_cast<uint32_t*>(&Pb[(size_t)gr1 * Nfull + gc]) =
                    *reinterpret_cast<uint32_t*>(&h1);
                s0 += e0 + e1;
                s1 += e2 + e3;
            }
            s0 += __shfl_xor_sync(~0u, s0, 1); s0 += __shfl_xor_sync(~0u, s0, 2);
            s1 += __shfl_xor_sync(~0u, s1, 1); s1 += __shfl_xor_sync(~0u, s1, 2);
            if (lc == 0) {
                int rl0 = wm * WMT + mf * 16 + lr;
                spart[wn * 128 + rl0]     = s0;
                spart[wn * 128 + rl0 + 8] = s1;
            }
        }
        __syncthreads();
        if (tid < 128) {
            float s = spart[tid] + spart[128 + tid] + spart[256 + tid] + spart[384 + tid];
            partial[(size_t)blockIdx.x * M_TOT + grow_base + m0 + tid] = s;
        }
    }
}

// ---------------------------------------------------------------------------
// bf16 GEMM (final): out = gamma[n]*((p @ hT^T)/rowsum[m]) + V.
// BK=64 halfs, 3-stage cp.async pipeline. (unchanged from R7)
// ---------------------------------------------------------------------------
__global__ __launch_bounds__(256) void gemm_bf16_o(
    const __nv_bfloat16* __restrict__ A, const __nv_bfloat16* __restrict__ Bm,
    float* __restrict__ C, int M, int Nfull, int K,
    const float* __restrict__ gamma, const float* __restrict__ vres,
    const float* __restrict__ rowsum, long sA, long sB, long sC, long sV)
{
    constexpr int NT = 128, LDA = 36;
    constexpr int BKH = 64;
    constexpr int WMT = 64, WNT = 32, MF = 4, NF = 4;
    constexpr int ASZ = 128 * LDA, BUF = ASZ + NT * LDA;

    extern __shared__ uint32_t smu[];
    const int tid = threadIdx.x, wid = tid >> 5, lane = tid & 31;
    const int lr = lane >> 2, lc = lane & 3;
    const int bz = blockIdx.z;

    A  += (size_t)bz * sA;
    Bm += (size_t)bz * sB;
    float* Cb = C + (size_t)bz * sC;
    const float* vres_b = vres + (size_t)bz * sV;
    const float* rs_b   = rowsum + (size_t)bz * M;

    const int m0 = blockIdx.y * 128, n0 = blockIdx.x * NT;
    const int wm = wid & 1, wn = wid >> 1;
    const uint32_t sbase = smem_u32(smu);

    float acc[MF][NF][4];
#pragma unroll
    for (int i = 0; i < MF; i++)
#pragma unroll
        for (int j = 0; j < NF; j++)
#pragma unroll
            for (int r = 0; r < 4; r++) acc[i][j][r] = 0.f;

    auto stage = [&](int k0, int buf) {
#pragma unroll
        for (int l = 0; l < 4; l++) {
            int idx = tid + l * 256;
            int r = idx >> 3, q = idx & 7;
            CP16(sbase + (uint32_t)(buf * BUF + r * LDA + q * 4) * 4,
                 A + (size_t)(m0 + r) * K + k0 + q * 8);
        }
#pragma unroll
        for (int l = 0; l < 4; l++) {
            int idx = tid + l * 256;
            int r = idx >> 3, q = idx & 7;
            CP16(sbase + (uint32_t)(buf * BUF + ASZ + r * LDA + q * 4) * 4,
                 Bm + (size_t)(n0 + r) * K + k0 + q * 8);
        }
        CP_COMMIT();
    };

    const int T = K / BKH;
    stage(0, 0);
    stage(BKH, 1);
    for (int t = 0; t < T; t++) {
        if (t + 2 < T) { stage((t + 2) * BKH, (t + 2) % 3); CP_WAIT2(); }
        else if (t + 1 < T) { CP_WAIT1(); }
        else { CP_WAIT0(); }
        __syncthreads();

        const uint32_t* As = smu + (t % 3) * BUF;
        const uint32_t* Bs = As + ASZ;
#pragma unroll
        for (int ks = 0; ks < 4; ks++) {
            const int kk = ks * 8 + lc;
            uint32_t a[MF][4], b[NF][2];
#pragma unroll
            for (int mf = 0; mf < MF; mf++) {
                const int r0 = (wm * WMT + mf * 16 + lr) * LDA;
                a[mf][0] = As[r0 + kk];
                a[mf][1] = As[r0 + 8 * LDA + kk];
                a[mf][2] = As[r0 + kk + 4];
                a[mf][3] = As[r0 + 8 * LDA + kk + 4];
            }
#pragma unroll
            for (int nf = 0; nf < NF; nf++) {
                const int r0 = (wn * WNT + nf * 8 + lr) * LDA;
                b[nf][0] = Bs[r0 + kk];
                b[nf][1] = Bs[r0 + kk + 4];
            }
#pragma unroll
            for (int mf = 0; mf < MF; mf++)
#pragma unroll
                for (int nf = 0; nf < NF; nf++)
                    mma_bf16(acc[mf][nf], a[mf], b[nf]);
        }
        __syncthreads();
    }

    const int mb = m0 + wm * WMT, nb = n0 + wn * WNT;
#pragma unroll
    for (int mf = 0; mf < MF; mf++) {
        const int gr0 = mb + mf * 16 + lr, gr1 = gr0 + 8;
        const float inv0 = 1.f / rs_b[gr0], inv1 = 1.f / rs_b[gr1];
#pragma unroll
        for (int nf = 0; nf < NF; nf++) {
            const int gc = nb + nf * 8 + 2 * lc;
            const float* d = acc[mf][nf];
            float2 vr0 = *reinterpret_cast<const float2*>(&vres_b[(size_t)gr0 * Nfull + gc]);
            float2 vr1 = *reinterpret_cast<const float2*>(&vres_b[(size_t)gr1 * Nfull + gc]);
            float2 gg  = *reinterpret_cast<const float2*>(&gamma[gc]);
            *reinterpret_cast<float2*>(&Cb[(size_t)gr0 * Nfull + gc]) =
                make_float2(fmaf(gg.x, d[0] * inv0, vr0.x), fmaf(gg.y, d[1] * inv0, vr0.y));
            *reinterpret_cast<float2*>(&Cb[(size_t)gr1 * Nfull + gc]) =
                make_float2(fmaf(gg.x, d[2] * inv1, vr1.x), fmaf(gg.y, d[3] * inv1, vr1.y));
        }
    }
}

// ---------------------------------------------------------------------------
// Small kernels
// ---------------------------------------------------------------------------
__global__ void transpose_k(const float* __restrict__ in, float* __restrict__ out,
                            int R, int Ccols)
{
    __shared__ float t[32][33];
    const int c0 = blockIdx.x * 32, r0 = blockIdx.y * 32;
    const int x = threadIdx.x, y = threadIdx.y;
#pragma unroll
    for (int i = 0; i < 32; i += 8)
        t[y + i][x] = in[(size_t)(r0 + y + i) * Ccols + c0 + x];
    __syncthreads();
#pragma unroll
    for (int i = 0; i < 32; i += 8)
        out[(size_t)(c0 + y + i) * R + r0 + x] = tf32r(t[x][y + i]);
}

__global__ void cat_bias_k(const float* __restrict__ a, const float* __restrict__ b,
                           float* __restrict__ out)
{
    int t = threadIdx.x;
    out[t] = (t < 64) ? a[t] : b[t - 64];
}

__global__ void zero_maxg_k(int* __restrict__ mg) { mg[threadIdx.x] = 0; }

// Per-row norms of f (cols 0..63) and g (cols 64..127); atomicMax of ||g|| per
// batch (int-encoded nonneg float: order-independent -> deterministic).
__global__ __launch_bounds__(256) void norms_k(const float* __restrict__ fg,
                                               float* __restrict__ normf,
                                               int* __restrict__ maxg)
{
    int row = blockIdx.x * 8 + (threadIdx.x >> 5);
    int lane = threadIdx.x & 31;
    const float* r = fg + (size_t)row * 128;
    float f0 = r[lane], f1 = r[lane + 32];
    float g0 = r[lane + 64], g1 = r[lane + 96];
    float sf = f0 * f0 + f1 * f1, sg = g0 * g0 + g1 * g1;
#pragma unroll
    for (int o = 16; o; o >>= 1) {
        sf += __shfl_xor_sync(~0u, sf, o);
        sg += __shfl_xor_sync(~0u, sg, o);
    }
    if (lane == 0) {
        normf[row] = sqrtf(sf);
        atomicMax(&maxg[row >> 12], __float_as_int(sqrtf(sg)));
    }
}

__global__ __launch_bounds__(256) void reduce_rs_k(const float* __restrict__ partial,
                                                   float* __restrict__ rs)
{
    int i = blockIdx.x * 256 + threadIdx.x;
    float s = 0.f;
#pragma unroll
    for (int nt = 0; nt < 32; nt++) s += partial[(size_t)nt * M_TOT + i];
    rs[i] = s;
}

// ---------------------------------------------------------------------------
extern "C" void kernel_launch(void* const* d_in, const int* in_sizes, int n_in,
                              void* d_out, int out_size)
{
    const float* V  = (const float*)d_in[0];
    const float* Wf = (const float*)d_in[1];
    const float* bf = (const float*)d_in[2];
    const float* Wg = (const float*)d_in[3];
    const float* bg = (const float*)d_in[4];
    const float* Wh = (const float*)d_in[5];
    const float* bh = (const float*)d_in[6];
    const float* gm = (const float*)d_in[7];
    float* out = (float*)d_out;

    float *fgP, *partP, *rsP, *normfP, *bfgP, *wfgT, *whT;
    int* maxgP;
    __nv_bfloat16 *hTP, *pP;
    cudaGetSymbolAddress((void**)&fgP,   g_fg);
    cudaGetSymbolAddress((void**)&hTP,   g_hT);
    cudaGetSymbolAddress((void**)&pP,    g_p);
    cudaGetSymbolAddress((void**)&partP, g_part);
    cudaGetSymbolAddress((void**)&rsP,   g_rs);
    cudaGetSymbolAddress((void**)&normfP,g_normf);
    cudaGetSymbolAddress((void**)&maxgP, g_maxg);
    cudaGetSymbolAddress((void**)&bfgP,  g_bfg);
    cudaGetSymbolAddress((void**)&wfgT,  g_wfgT);
    cudaGetSymbolAddress((void**)&whT,   g_whT);

    const int SM_TF = 2 * (128 + 128) * 36 * 4;   // 73728 B
    const int SM_BF = 3 * (128 + 128) * 36 * 4;   // 110592 B

    cudaFuncSetAttribute(gemm_tf32<128, 1, true>,
                         cudaFuncAttributeMaxDynamicSharedMemorySize, SM_TF);
    cudaFuncSetAttribute(gemm_tf32<128, 5, true>,
                         cudaFuncAttributeMaxDynamicSharedMemorySize, SM_TF);
    cudaFuncSetAttribute(gemm_tf32<128, 6, false>,
                         cudaFuncAttributeMaxDynamicSharedMemorySize, SM_TF);
    cudaFuncSetAttribute(gemm_bf16_o,
                         cudaFuncAttributeMaxDynamicSharedMemorySize, SM_BF);

    dim3 blk(256);
    dim3 tb(32, 8);

    // Stacked [WfT; WgT] -> wfgT [128,512]; whT [512,512]; stacked bias.
    transpose_k<<<dim3(C_ / 32, F_ / 32), tb>>>(Wf, wfgT, F_, C_);
    transpose_k<<<dim3(C_ / 32, F_ / 32), tb>>>(Wg, wfgT + 64 * F_, F_, C_);
    transpose_k<<<dim3(F_ / 32, F_ / 32), tb>>>(Wh, whT, F_, F_);
    cat_bias_k<<<1, 128>>>(bf, bg, bfgP);
    zero_maxg_k<<<1, B_>>>(maxgP);

    // fg = relu(V @ [Wf|Wg] + [bf|bg])  [16384, 128]
    gemm_tf32<128, 1, true><<<dim3(1, 128, 1), blk, SM_TF>>>(
        V, wfgT, fgP, M_TOT, 128, F_, F_, F_, bfgP,
        nullptr, nullptr, nullptr, 0, 0, 0);

    // row norms of f, per-batch max ||g||
    norms_k<<<M_TOT / 8, blk>>>(fgP, normfP, maxgP);

    // hT[b][f][n] = bf16(relu(V@Wh+bh)) transposed per batch
    gemm_tf32<128, 5, true><<<dim3(4, 128, 1), blk, SM_TF>>>(
        V, whT, (float*)hTP, M_TOT, F_, F_, F_, F_, bh,
        nullptr, nullptr, nullptr, 0, 0, 0);

    // scores + fused exp: p = bf16(exp(f@g^T - M_row)), partial rowsums
    gemm_tf32<128, 6, false><<<dim3(32, 32, B_), blk, SM_TF>>>(
        fgP, fgP + 64, (float*)pP, N_, N_, C_, 128, 128, nullptr,
        normfP, maxgP, partP,
        (long)N_ * 128, (long)N_ * 128, (long)N_ * N_);

    // rowsum = sum of 32 n-tile partials (deterministic)
    reduce_rs_k<<<M_TOT / 256, blk>>>(partP, rsP);

    // out = gamma * (p @ h / rowsum) + V
    gemm_bf16_o<<<dim3(4, 32, B_), blk, SM_BF>>>(
        pP, hTP, out, N_, F_, N_, gm, V, rsP,
        (long)N_ * N_, (long)F_ * N_, (long)N_ * F_, (long)N_ * F_);
}

// round 11
// speedup vs baseline: 9.3425x; 1.1273x over previous
// R10: scheduling-only round. o-GEMM 3-stage/108KB -> 2-stage/72KB so 2 CTAs
// co-reside per SM (16 warps, hides sync/latency gaps; launch_bounds(256,2)).
// Small-kernel merges: cat_bias+zero_maxg -> prep_k; Wf/Wg transposes -> one
// launch. Arithmetic bit-identical to R9 (rel_err margin is thin).
#include <cuda_runtime.h>
#include <cuda_bf16.h>
#include <cstdint>
#include <math.h>

#define B_    4
#define N_    4096
#define F_    512
#define C_    64
#define M_TOT (B_ * N_)   // 16384

// ---------------- scratch (allocation-free) ----------------
__device__ float g_fg[(size_t)M_TOT * 128];              //  8 MiB [f|g] tf32
__device__ __nv_bfloat16 g_hT[(size_t)M_TOT * F_];       // 16 MiB, [B][F][N] bf16
__device__ __nv_bfloat16 g_p[(size_t)M_TOT * N_];        // 128 MiB exp(bf16)
__device__ float g_part[(size_t)32 * M_TOT];             //  2 MiB partial rowsums
__device__ float g_rs[M_TOT];
__device__ float g_normf[M_TOT];
__device__ int   g_maxg[B_];
__device__ float g_bfg[128];
__device__ float g_wfgT[128 * F_];                       // stacked [WfT; WgT]
__device__ float g_whT[F_ * F_];

// ---------------- helpers ----------------
__device__ __forceinline__ float tf32r(float x) {
    uint32_t u;
    asm("cvt.rna.tf32.f32 %0, %1;" : "=r"(u) : "f"(x));
    return __uint_as_float(u);
}
__device__ __forceinline__ uint32_t smem_u32(const void* p) {
    uint32_t a;
    asm("{ .reg .u64 t; cvta.to.shared.u64 t, %1; cvt.u32.u64 %0, t; }" : "=r"(a) : "l"(p));
    return a;
}
#define CP16(dst, src) \
    asm volatile("cp.async.ca.shared.global [%0], [%1], 16;" :: "r"(dst), "l"(src))
#define CP_COMMIT() asm volatile("cp.async.commit_group;" ::: "memory")
#define CP_WAIT1()  asm volatile("cp.async.wait_group 1;" ::: "memory")
#define CP_WAIT0()  asm volatile("cp.async.wait_group 0;" ::: "memory")

__device__ __forceinline__ void mma_tf32(float* d, const float* a, const float* b) {
    asm volatile(
        "mma.sync.aligned.m16n8k8.row.col.f32.tf32.tf32.f32 "
        "{%0,%1,%2,%3}, {%4,%5,%6,%7}, {%8,%9}, {%0,%1,%2,%3};"
        : "+f"(d[0]), "+f"(d[1]), "+f"(d[2]), "+f"(d[3])
        : "r"(__float_as_uint(a[0])), "r"(__float_as_uint(a[1])),
          "r"(__float_as_uint(a[2])), "r"(__float_as_uint(a[3])),
          "r"(__float_as_uint(b[0])), "r"(__float_as_uint(b[1])));
}
__device__ __forceinline__ void mma_bf16(float* d, const uint32_t* a, const uint32_t* b) {
    asm volatile(
        "mma.sync.aligned.m16n8k16.row.col.f32.bf16.bf16.f32 "
        "{%0,%1,%2,%3}, {%4,%5,%6,%7}, {%8,%9}, {%0,%1,%2,%3};"
        : "+f"(d[0]), "+f"(d[1]), "+f"(d[2]), "+f"(d[3])
        : "r"(a[0]), "r"(a[1]), "r"(a[2]), "r"(a[3]), "r"(b[0]), "r"(b[1]));
}

// ---------------------------------------------------------------------------
// tf32 GEMM: C[M, Nfull] = A[M,K] @ B^T, B stored [Nfull rows, K] with row
// stride ldB; A row stride ldA. BK=32, LDS=36 floats, 2-stage cp.async.
// RA: round A frags to tf32 in-register.
// MODE 1: fp32 tf32r(relu(acc+bias)) -> C.
// MODE 5: bf16 relu(acc+bias) written transposed per batch (h path).
// MODE 6: p = bf16(exp(acc - normf[row]*maxg[bz])) -> C (bf16, batch stride sC
//         in halfs); deterministic partial rowsums -> partial[blockIdx.x][row].
// ---------------------------------------------------------------------------
template <int NT, int MODE, bool RA>
__global__ __launch_bounds__(256) void gemm_tf32(
    const float* __restrict__ A, const float* __restrict__ Bm, float* __restrict__ C,
    int M, int Nfull, int K, int ldA, int ldB,
    const float* __restrict__ bias,
    const float* __restrict__ normf, const int* __restrict__ maxg,
    float* __restrict__ partial,
    long sA, long sB, long sC)
{
    constexpr int BK = 32, LDS = 36;
    constexpr int WN_WARPS = 4, WM_WARPS = 2;
    constexpr int WMT = 64;
    constexpr int WNT = NT / WN_WARPS;
    constexpr int MF = 4, NF = WNT / 8;
    constexpr int ASZ = 128 * LDS, BUF = ASZ + NT * LDS;
    constexpr int LB = NT / 32;

    extern __shared__ float sm[];
    const int tid = threadIdx.x, wid = tid >> 5, lane = tid & 31;
    const int lr = lane >> 2, lc = lane & 3;
    const int bz = blockIdx.z;

    A  += (size_t)bz * sA;
    Bm += (size_t)bz * sB;
    float* Cb = C;
    if (MODE == 1) Cb = C + (size_t)bz * sC;

    const int m0 = blockIdx.y * 128, n0 = blockIdx.x * NT;
    const int wm = wid % WM_WARPS, wn = wid / WM_WARPS;
    const uint32_t sbase = smem_u32(sm);

    float acc[MF][NF][4];
#pragma unroll
    for (int i = 0; i < MF; i++)
#pragma unroll
        for (int j = 0; j < NF; j++)
#pragma unroll
            for (int r = 0; r < 4; r++) acc[i][j][r] = 0.f;

    auto stage = [&](int k0, int buf) {
#pragma unroll
        for (int l = 0; l < 4; l++) {                 // A: 128 rows x 32 floats
            int idx = tid + l * 256;
            int r = idx >> 3, q = idx & 7;
            CP16(sbase + (uint32_t)(buf * BUF + r * LDS + q * 4) * 4,
                 A + (size_t)(m0 + r) * ldA + k0 + q * 4);
        }
#pragma unroll
        for (int l = 0; l < LB; l++) {                // B: NT rows x 32 floats
            int idx = tid + l * 256;
            int r = idx >> 3, q = idx & 7;
            CP16(sbase + (uint32_t)(buf * BUF + ASZ + r * LDS + q * 4) * 4,
                 Bm + (size_t)(n0 + r) * ldB + k0 + q * 4);
        }
        CP_COMMIT();
    };

    const int T = K / BK;
    stage(0, 0);
    for (int t = 0; t < T; t++) {
        if (t + 1 < T) { stage((t + 1) * BK, (t + 1) & 1); CP_WAIT1(); }
        else            { CP_WAIT0(); }
        __syncthreads();

        const float* As = sm + (t & 1) * BUF;
        const float* Bs = As + ASZ;
#pragma unroll
        for (int ks = 0; ks < BK / 8; ks++) {
            const int kk = ks * 8 + lc;
            float a[MF][4], b[NF][2];
#pragma unroll
            for (int mf = 0; mf < MF; mf++) {
                const int r0 = (wm * WMT + mf * 16 + lr) * LDS;
                a[mf][0] = As[r0 + kk];
                a[mf][1] = As[r0 + 8 * LDS + kk];
                a[mf][2] = As[r0 + kk + 4];
                a[mf][3] = As[r0 + 8 * LDS + kk + 4];
                if (RA) {
#pragma unroll
                    for (int r = 0; r < 4; r++) a[mf][r] = tf32r(a[mf][r]);
                }
            }
#pragma unroll
            for (int nf = 0; nf < NF; nf++) {
                const int r0 = (wn * WNT + nf * 8 + lr) * LDS;
                b[nf][0] = Bs[r0 + kk];
                b[nf][1] = Bs[r0 + kk + 4];
            }
#pragma unroll
            for (int mf = 0; mf < MF; mf++)
#pragma unroll
                for (int nf = 0; nf < NF; nf++)
                    mma_tf32(acc[mf][nf], a[mf], b[nf]);
        }
        __syncthreads();
    }

    const int mb = m0 + wm * WMT, nb = n0 + wn * WNT;

    if (MODE == 1) {
#pragma unroll
        for (int mf = 0; mf < MF; mf++) {
            const int gr0 = mb + mf * 16 + lr, gr1 = gr0 + 8;
#pragma unroll
            for (int nf = 0; nf < NF; nf++) {
                const int gc = nb + nf * 8 + 2 * lc;
                const float* d = acc[mf][nf];
                *reinterpret_cast<float2*>(&Cb[(size_t)gr0 * Nfull + gc]) =
                    make_float2(tf32r(fmaxf(d[0] + bias[gc], 0.f)),
                                tf32r(fmaxf(d[1] + bias[gc + 1], 0.f)));
                *reinterpret_cast<float2*>(&Cb[(size_t)gr1 * Nfull + gc]) =
                    make_float2(tf32r(fmaxf(d[2] + bias[gc], 0.f)),
                                tf32r(fmaxf(d[3] + bias[gc + 1], 0.f)));
            }
        }
    } else if (MODE == 5) {
        __nv_bfloat16* Ct = (__nv_bfloat16*)C;
#pragma unroll
        for (int mf = 0; mf < MF; mf++) {
            const int gr0 = mb + mf * 16 + lr, gr1 = gr0 + 8;
#pragma unroll
            for (int nf = 0; nf < NF; nf++) {
                const int gc = nb + nf * 8 + 2 * lc;
                const float* d = acc[mf][nf];
                float v0 = fmaxf(d[0] + bias[gc], 0.f);
                float v1 = fmaxf(d[1] + bias[gc + 1], 0.f);
                float v2 = fmaxf(d[2] + bias[gc], 0.f);
                float v3 = fmaxf(d[3] + bias[gc + 1], 0.f);
                size_t b0 = ((size_t)(gr0 >> 12) * Nfull);
                size_t b1 = ((size_t)(gr1 >> 12) * Nfull);
                Ct[(b0 + gc)     * 4096 + (gr0 & 4095)] = __float2bfloat16_rn(v0);
                Ct[(b0 + gc + 1) * 4096 + (gr0 & 4095)] = __float2bfloat16_rn(v1);
                Ct[(b1 + gc)     * 4096 + (gr1 & 4095)] = __float2bfloat16_rn(v2);
                Ct[(b1 + gc + 1) * 4096 + (gr1 & 4095)] = __float2bfloat16_rn(v3);
            }
        }
    } else {  // MODE 6
        __nv_bfloat16* Pb = (__nv_bfloat16*)C + (size_t)bz * sC;
        float* spart = sm;                    // reuse smem (all reads done)
        const float Mg = __int_as_float(maxg[bz]);
        const int grow_base = bz * 4096;
#pragma unroll
        for (int mf = 0; mf < MF; mf++) {
            const int gr0 = mb + mf * 16 + lr, gr1 = gr0 + 8;
            const float M0 = normf[grow_base + gr0] * Mg;
            const float M1 = normf[grow_base + gr1] * Mg;
            float s0 = 0.f, s1 = 0.f;
#pragma unroll
            for (int nf = 0; nf < NF; nf++) {
                const int gc = nb + nf * 8 + 2 * lc;
                const float* d = acc[mf][nf];
                float e0 = __expf(d[0] - M0), e1 = __expf(d[1] - M0);
                float e2 = __expf(d[2] - M1), e3 = __expf(d[3] - M1);
                __nv_bfloat162 h0 = __floats2bfloat162_rn(e0, e1);
                __nv_bfloat162 h1 = __floats2bfloat162_rn(e2, e3);
                *reinterpret_cast<uint32_t*>(&Pb[(size_t)gr0 * Nfull + gc]) =
                    *reinterpret_cast<uint32_t*>(&h0);
                *reinterpret_cast<uint32_t*>(&Pb[(size_t)gr1 * Nfull + gc]) =
                    *reinterpret_cast<uint32_t*>(&h1);
                s0 += e0 + e1;
                s1 += e2 + e3;
            }
            s0 += __shfl_xor_sync(~0u, s0, 1); s0 += __shfl_xor_sync(~0u, s0, 2);
            s1 += __shfl_xor_sync(~0u, s1, 1); s1 += __shfl_xor_sync(~0u, s1, 2);
            if (lc == 0) {
                int rl0 = wm * WMT + mf * 16 + lr;
                spart[wn * 128 + rl0]     = s0;
                spart[wn * 128 + rl0 + 8] = s1;
            }
        }
        __syncthreads();
        if (tid < 128) {
            float s = spart[tid] + spart[128 + tid] + spart[256 + tid] + spart[384 + tid];
            partial[(size_t)blockIdx.x * M_TOT + grow_base + m0 + tid] = s;
        }
    }
}

// ---------------------------------------------------------------------------
// bf16 GEMM (final): out = gamma[n]*((p @ hT^T)/rowsum[m]) + V.
// BK=64 halfs, 2-stage cp.async (72KB smem -> 2 CTAs/SM, 16 warps).
// ---------------------------------------------------------------------------
__global__ __launch_bounds__(256, 2) void gemm_bf16_o(
    const __nv_bfloat16* __restrict__ A, const __nv_bfloat16* __restrict__ Bm,
    float* __restrict__ C, int M, int Nfull, int K,
    const float* __restrict__ gamma, const float* __restrict__ vres,
    const float* __restrict__ rowsum, long sA, long sB, long sC, long sV)
{
    constexpr int NT = 128, LDA = 36;
    constexpr int BKH = 64;
    constexpr int WMT = 64, WNT = 32, MF = 4, NF = 4;
    constexpr int ASZ = 128 * LDA, BUF = ASZ + NT * LDA;

    extern __shared__ uint32_t smu[];
    const int tid = threadIdx.x, wid = tid >> 5, lane = tid & 31;
    const int lr = lane >> 2, lc = lane & 3;
    const int bz = blockIdx.z;

    A  += (size_t)bz * sA;
    Bm += (size_t)bz * sB;
    float* Cb = C + (size_t)bz * sC;
    const float* vres_b = vres + (size_t)bz * sV;
    const float* rs_b   = rowsum + (size_t)bz * M;

    const int m0 = blockIdx.y * 128, n0 = blockIdx.x * NT;
    const int wm = wid & 1, wn = wid >> 1;
    const uint32_t sbase = smem_u32(smu);

    float acc[MF][NF][4];
#pragma unroll
    for (int i = 0; i < MF; i++)
#pragma unroll
        for (int j = 0; j < NF; j++)
#pragma unroll
            for (int r = 0; r < 4; r++) acc[i][j][r] = 0.f;

    auto stage = [&](int k0, int buf) {
#pragma unroll
        for (int l = 0; l < 4; l++) {
            int idx = tid + l * 256;
            int r = idx >> 3, q = idx & 7;
            CP16(sbase + (uint32_t)(buf * BUF + r * LDA + q * 4) * 4,
                 A + (size_t)(m0 + r) * K + k0 + q * 8);
        }
#pragma unroll
        for (int l = 0; l < 4; l++) {
            int idx = tid + l * 256;
            int r = idx >> 3, q = idx & 7;
            CP16(sbase + (uint32_t)(buf * BUF + ASZ + r * LDA + q * 4) * 4,
                 Bm + (size_t)(n0 + r) * K + k0 + q * 8);
        }
        CP_COMMIT();
    };

    const int T = K / BKH;
    stage(0, 0);
    for (int t = 0; t < T; t++) {
        if (t + 1 < T) { stage((t + 1) * BKH, (t + 1) & 1); CP_WAIT1(); }
        else            { CP_WAIT0(); }
        __syncthreads();

        const uint32_t* As = smu + (t & 1) * BUF;
        const uint32_t* Bs = As + ASZ;
#pragma unroll
        for (int ks = 0; ks < 4; ks++) {
            const int kk = ks * 8 + lc;
            uint32_t a[MF][4], b[NF][2];
#pragma unroll
            for (int mf = 0; mf < MF; mf++) {
                const int r0 = (wm * WMT + mf * 16 + lr) * LDA;
                a[mf][0] = As[r0 + kk];
                a[mf][1] = As[r0 + 8 * LDA + kk];
                a[mf][2] = As[r0 + kk + 4];
                a[mf][3] = As[r0 + 8 * LDA + kk + 4];
            }
#pragma unroll
            for (int nf = 0; nf < NF; nf++) {
                const int r0 = (wn * WNT + nf * 8 + lr) * LDA;
                b[nf][0] = Bs[r0 + kk];
                b[nf][1] = Bs[r0 + kk + 4];
            }
#pragma unroll
            for (int mf = 0; mf < MF; mf++)
#pragma unroll
                for (int nf = 0; nf < NF; nf++)
                    mma_bf16(acc[mf][nf], a[mf], b[nf]);
        }
        __syncthreads();
    }

    const int mb = m0 + wm * WMT, nb = n0 + wn * WNT;
#pragma unroll
    for (int mf = 0; mf < MF; mf++) {
        const int gr0 = mb + mf * 16 + lr, gr1 = gr0 + 8;
        const float inv0 = 1.f / rs_b[gr0], inv1 = 1.f / rs_b[gr1];
#pragma unroll
        for (int nf = 0; nf < NF; nf++) {
            const int gc = nb + nf * 8 + 2 * lc;
            const float* d = acc[mf][nf];
            float2 vr0 = *reinterpret_cast<const float2*>(&vres_b[(size_t)gr0 * Nfull + gc]);
            float2 vr1 = *reinterpret_cast<const float2*>(&vres_b[(size_t)gr1 * Nfull + gc]);
            float2 gg  = *reinterpret_cast<const float2*>(&gamma[gc]);
            *reinterpret_cast<float2*>(&Cb[(size_t)gr0 * Nfull + gc]) =
                make_float2(fmaf(gg.x, d[0] * inv0, vr0.x), fmaf(gg.y, d[1] * inv0, vr0.y));
            *reinterpret_cast<float2*>(&Cb[(size_t)gr1 * Nfull + gc]) =
                make_float2(fmaf(gg.x, d[2] * inv1, vr1.x), fmaf(gg.y, d[3] * inv1, vr1.y));
        }
    }
}

// ---------------------------------------------------------------------------
// Small kernels
// ---------------------------------------------------------------------------
__global__ void transpose_k(const float* __restrict__ in, float* __restrict__ out,
                            int R, int Ccols)
{
    __shared__ float t[32][33];
    const int c0 = blockIdx.x * 32, r0 = blockIdx.y * 32;
    const int x = threadIdx.x, y = threadIdx.y;
#pragma unroll
    for (int i = 0; i < 32; i += 8)
        t[y + i][x] = in[(size_t)(r0 + y + i) * Ccols + c0 + x];
    __syncthreads();
#pragma unroll
    for (int i = 0; i < 32; i += 8)
        out[(size_t)(c0 + y + i) * R + r0 + x] = tf32r(t[x][y + i]);
}

// Transpose two [F,C] weights into stacked wfgT [128,512] in one launch.
__global__ void transpose2_k(const float* __restrict__ inA, const float* __restrict__ inB,
                             float* __restrict__ out, int R, int Ccols)
{
    __shared__ float t[32][33];
    const float* in = blockIdx.z ? inB : inA;
    float* o = out + (size_t)blockIdx.z * Ccols * R;   // slab offset (64*512)
    const int c0 = blockIdx.x * 32, r0 = blockIdx.y * 32;
    const int x = threadIdx.x, y = threadIdx.y;
#pragma unroll
    for (int i = 0; i < 32; i += 8)
        t[y + i][x] = in[(size_t)(r0 + y + i) * Ccols + c0 + x];
    __syncthreads();
#pragma unroll
    for (int i = 0; i < 32; i += 8)
        o[(size_t)(c0 + y + i) * R + r0 + x] = tf32r(t[x][y + i]);
}

// bias concat + maxg zero, one launch
__global__ void prep_k(const float* __restrict__ a, const float* __restrict__ b,
                       float* __restrict__ out, int* __restrict__ mg)
{
    int t = threadIdx.x;
    out[t] = (t < 64) ? a[t] : b[t - 64];
    if (t < B_) mg[t] = 0;
}

// Per-row norms of f (cols 0..63) and g (cols 64..127); atomicMax of ||g|| per
// batch (int-encoded nonneg float: order-independent -> deterministic).
__global__ __launch_bounds__(256) void norms_k(const float* __restrict__ fg,
                                               float* __restrict__ normf,
                                               int* __restrict__ maxg)
{
    int row = blockIdx.x * 8 + (threadIdx.x >> 5);
    int lane = threadIdx.x & 31;
    const float* r = fg + (size_t)row * 128;
    float f0 = r[lane], f1 = r[lane + 32];
    float g0 = r[lane + 64], g1 = r[lane + 96];
    float sf = f0 * f0 + f1 * f1, sg = g0 * g0 + g1 * g1;
#pragma unroll
    for (int o = 16; o; o >>= 1) {
        sf += __shfl_xor_sync(~0u, sf, o);
        sg += __shfl_xor_sync(~0u, sg, o);
    }
    if (lane == 0) {
        normf[row] = sqrtf(sf);
        atomicMax(&maxg[row >> 12], __float_as_int(sqrtf(sg)));
    }
}

__global__ __launch_bounds__(256) void reduce_rs_k(const float* __restrict__ partial,
                                                   float* __restrict__ rs)
{
    int i = blockIdx.x * 256 + threadIdx.x;
    float s = 0.f;
#pragma unroll
    for (int nt = 0; nt < 32; nt++) s += partial[(size_t)nt * M_TOT + i];
    rs[i] = s;
}

// ---------------------------------------------------------------------------
extern "C" void kernel_launch(void* const* d_in, const int* in_sizes, int n_in,
                              void* d_out, int out_size)
{
    const float* V  = (const float*)d_in[0];
    const float* Wf = (const float*)d_in[1];
    const float* bf = (const float*)d_in[2];
    const float* Wg = (const float*)d_in[3];
    const float* bg = (const float*)d_in[4];
    const float* Wh = (const float*)d_in[5];
    const float* bh = (const float*)d_in[6];
    const float* gm = (const float*)d_in[7];
    float* out = (float*)d_out;

    float *fgP, *partP, *rsP, *normfP, *bfgP, *wfgT, *whT;
    int* maxgP;
    __nv_bfloat16 *hTP, *pP;
    cudaGetSymbolAddress((void**)&fgP,   g_fg);
    cudaGetSymbolAddress((void**)&hTP,   g_hT);
    cudaGetSymbolAddress((void**)&pP,    g_p);
    cudaGetSymbolAddress((void**)&partP, g_part);
    cudaGetSymbolAddress((void**)&rsP,   g_rs);
    cudaGetSymbolAddress((void**)&normfP,g_normf);
    cudaGetSymbolAddress((void**)&maxgP, g_maxg);
    cudaGetSymbolAddress((void**)&bfgP,  g_bfg);
    cudaGetSymbolAddress((void**)&wfgT,  g_wfgT);
    cudaGetSymbolAddress((void**)&whT,   g_whT);

    const int SM_TF = 2 * (128 + 128) * 36 * 4;   // 73728 B
    const int SM_BF = 2 * (128 + 128) * 36 * 4;   // 73728 B (2-stage)

    cudaFuncSetAttribute(gemm_tf32<128, 1, true>,
                         cudaFuncAttributeMaxDynamicSharedMemorySize, SM_TF);
    cudaFuncSetAttribute(gemm_tf32<128, 5, true>,
                         cudaFuncAttributeMaxDynamicSharedMemorySize, SM_TF);
    cudaFuncSetAttribute(gemm_tf32<128, 6, false>,
                         cudaFuncAttributeMaxDynamicSharedMemorySize, SM_TF);
    cudaFuncSetAttribute(gemm_bf16_o,
                         cudaFuncAttributeMaxDynamicSharedMemorySize, SM_BF);

    dim3 blk(256);
    dim3 tb(32, 8);

    // Stacked [WfT; WgT] -> wfgT (one launch, z=2); whT; bias concat + maxg=0.
    transpose2_k<<<dim3(C_ / 32, F_ / 32, 2), tb>>>(Wf, Wg, wfgT, F_, C_);
    transpose_k<<<dim3(F_ / 32, F_ / 32), tb>>>(Wh, whT, F_, F_);
    prep_k<<<1, 128>>>(bf, bg, bfgP, maxgP);

    // fg = relu(V @ [Wf|Wg] + [bf|bg])  [16384, 128]
    gemm_tf32<128, 1, true><<<dim3(1, 128, 1), blk, SM_TF>>>(
        V, wfgT, fgP, M_TOT, 128, F_, F_, F_, bfgP,
        nullptr, nullptr, nullptr, 0, 0, 0);

    // row norms of f, per-batch max ||g||
    norms_k<<<M_TOT / 8, blk>>>(fgP, normfP, maxgP);

    // hT[b][f][n] = bf16(relu(V@Wh+bh)) transposed per batch
    gemm_tf32<128, 5, true><<<dim3(4, 128, 1), blk, SM_TF>>>(
        V, whT, (float*)hTP, M_TOT, F_, F_, F_, F_, bh,
        nullptr, nullptr, nullptr, 0, 0, 0);

    // scores + fused exp: p = bf16(exp(f@g^T - M_row)), partial rowsums
    gemm_tf32<128, 6, false><<<dim3(32, 32, B_), blk, SM_TF>>>(
        fgP, fgP + 64, (float*)pP, N_, N_, C_, 128, 128, nullptr,
        normfP, maxgP, partP,
        (long)N_ * 128, (long)N_ * 128, (long)N_ * N_);

    // rowsum = sum of 32 n-tile partials (deterministic)
    reduce_rs_k<<<M_TOT / 256, blk>>>(partP, rsP);

    // out = gamma * (p @ h / rowsum) + V
    gemm_bf16_o<<<dim3(4, 32, B_), blk, SM_BF>>>(
        pP, hTP, out, N_, F_, N_, gm, V, rsP,
        (long)N_ * N_, (long)F_ * N_, (long)N_ * F_, (long)N_ * F_);
}

// round 13
// speedup vs baseline: 9.5307x; 1.0201x over previous
// R11: occupancy round for the tf32 GEMMs (__launch_bounds__(256,2), confirmed
// lever from R10's o-GEMM) + norms fused into the fg epilogue (MODE 7; kills
// norms_k launch). M_i now derives from unrounded epilogue values: the shift
// cancels in the softmax ratio and cannot overflow. o-GEMM unchanged.
#include <cuda_runtime.h>
#include <cuda_bf16.h>
#include <cstdint>
#include <math.h>

#define B_    4
#define N_    4096
#define F_    512
#define C_    64
#define M_TOT (B_ * N_)   // 16384

// ---------------- scratch (allocation-free) ----------------
__device__ float g_fg[(size_t)M_TOT * 128];              //  8 MiB [f|g] tf32
__device__ __nv_bfloat16 g_hT[(size_t)M_TOT * F_];       // 16 MiB, [B][F][N] bf16
__device__ __nv_bfloat16 g_p[(size_t)M_TOT * N_];        // 128 MiB exp(bf16)
__device__ float g_part[(size_t)32 * M_TOT];             //  2 MiB partial rowsums
__device__ float g_rs[M_TOT];
__device__ float g_normf[M_TOT];
__device__ int   g_maxg[B_];
__device__ float g_bfg[128];
__device__ float g_wfgT[128 * F_];                       // stacked [WfT; WgT]
__device__ float g_whT[F_ * F_];

// ---------------- helpers ----------------
__device__ __forceinline__ float tf32r(float x) {
    uint32_t u;
    asm("cvt.rna.tf32.f32 %0, %1;" : "=r"(u) : "f"(x));
    return __uint_as_float(u);
}
__device__ __forceinline__ uint32_t smem_u32(const void* p) {
    uint32_t a;
    asm("{ .reg .u64 t; cvta.to.shared.u64 t, %1; cvt.u32.u64 %0, t; }" : "=r"(a) : "l"(p));
    return a;
}
#define CP16(dst, src) \
    asm volatile("cp.async.ca.shared.global [%0], [%1], 16;" :: "r"(dst), "l"(src))
#define CP_COMMIT() asm volatile("cp.async.commit_group;" ::: "memory")
#define CP_WAIT1()  asm volatile("cp.async.wait_group 1;" ::: "memory")
#define CP_WAIT0()  asm volatile("cp.async.wait_group 0;" ::: "memory")

__device__ __forceinline__ void mma_tf32(float* d, const float* a, const float* b) {
    asm volatile(
        "mma.sync.aligned.m16n8k8.row.col.f32.tf32.tf32.f32 "
        "{%0,%1,%2,%3}, {%4,%5,%6,%7}, {%8,%9}, {%0,%1,%2,%3};"
        : "+f"(d[0]), "+f"(d[1]), "+f"(d[2]), "+f"(d[3])
        : "r"(__float_as_uint(a[0])), "r"(__float_as_uint(a[1])),
          "r"(__float_as_uint(a[2])), "r"(__float_as_uint(a[3])),
          "r"(__float_as_uint(b[0])), "r"(__float_as_uint(b[1])));
}
__device__ __forceinline__ void mma_bf16(float* d, const uint32_t* a, const uint32_t* b) {
    asm volatile(
        "mma.sync.aligned.m16n8k16.row.col.f32.bf16.bf16.f32 "
        "{%0,%1,%2,%3}, {%4,%5,%6,%7}, {%8,%9}, {%0,%1,%2,%3};"
        : "+f"(d[0]), "+f"(d[1]), "+f"(d[2]), "+f"(d[3])
        : "r"(a[0]), "r"(a[1]), "r"(a[2]), "r"(a[3]), "r"(b[0]), "r"(b[1]));
}

// ---------------------------------------------------------------------------
// tf32 GEMM: C[M, Nfull] = A[M,K] @ B^T, B stored [Nfull rows, K] with row
// stride ldB; A row stride ldA. BK=32, LDS=36 floats, 2-stage cp.async,
// 2 CTAs/SM. RA: round A frags to tf32 in-register.
// MODE 5: bf16 relu(acc+bias) written transposed per batch (h path).
// MODE 6: p = bf16(exp(acc - normf[row]*maxg[bz])); partial rowsums out.
// MODE 7: fp32 tf32r(relu(acc+bias)) -> C, PLUS fused row norms:
//         partial[row] = ||f_row||, atomicMax(maxg[batch], ||g_row||).
// ---------------------------------------------------------------------------
template <int NT, int MODE, bool RA>
__global__ __launch_bounds__(256, 2) void gemm_tf32(
    const float* __restrict__ A, const float* __restrict__ Bm, float* __restrict__ C,
    int M, int Nfull, int K, int ldA, int ldB,
    const float* __restrict__ bias,
    const float* __restrict__ normf, int* __restrict__ maxg,
    float* __restrict__ partial,
    long sA, long sB, long sC)
{
    constexpr int BK = 32, LDS = 36;
    constexpr int WN_WARPS = 4, WM_WARPS = 2;
    constexpr int WMT = 64;
    constexpr int WNT = NT / WN_WARPS;
    constexpr int MF = 4, NF = WNT / 8;
    constexpr int ASZ = 128 * LDS, BUF = ASZ + NT * LDS;
    constexpr int LB = NT / 32;

    extern __shared__ float sm[];
    const int tid = threadIdx.x, wid = tid >> 5, lane = tid & 31;
    const int lr = lane >> 2, lc = lane & 3;
    const int bz = blockIdx.z;

    A  += (size_t)bz * sA;
    Bm += (size_t)bz * sB;
    float* Cb = C;
    if (MODE == 7) Cb = C + (size_t)bz * sC;

    const int m0 = blockIdx.y * 128, n0 = blockIdx.x * NT;
    const int wm = wid % WM_WARPS, wn = wid / WM_WARPS;
    const uint32_t sbase = smem_u32(sm);

    float acc[MF][NF][4];
#pragma unroll
    for (int i = 0; i < MF; i++)
#pragma unroll
        for (int j = 0; j < NF; j++)
#pragma unroll
            for (int r = 0; r < 4; r++) acc[i][j][r] = 0.f;

    auto stage = [&](int k0, int buf) {
#pragma unroll
        for (int l = 0; l < 4; l++) {                 // A: 128 rows x 32 floats
            int idx = tid + l * 256;
            int r = idx >> 3, q = idx & 7;
            CP16(sbase + (uint32_t)(buf * BUF + r * LDS + q * 4) * 4,
                 A + (size_t)(m0 + r) * ldA + k0 + q * 4);
        }
#pragma unroll
        for (int l = 0; l < LB; l++) {                // B: NT rows x 32 floats
            int idx = tid + l * 256;
            int r = idx >> 3, q = idx & 7;
            CP16(sbase + (uint32_t)(buf * BUF + ASZ + r * LDS + q * 4) * 4,
                 Bm + (size_t)(n0 + r) * ldB + k0 + q * 4);
        }
        CP_COMMIT();
    };

    const int T = K / BK;
    stage(0, 0);
    for (int t = 0; t < T; t++) {
        if (t + 1 < T) { stage((t + 1) * BK, (t + 1) & 1); CP_WAIT1(); }
        else            { CP_WAIT0(); }
        __syncthreads();

        const float* As = sm + (t & 1) * BUF;
        const float* Bs = As + ASZ;
#pragma unroll
        for (int ks = 0; ks < BK / 8; ks++) {
            const int kk = ks * 8 + lc;
            float a[MF][4], b[NF][2];
#pragma unroll
            for (int mf = 0; mf < MF; mf++) {
                const int r0 = (wm * WMT + mf * 16 + lr) * LDS;
                a[mf][0] = As[r0 + kk];
                a[mf][1] = As[r0 + 8 * LDS + kk];
                a[mf][2] = As[r0 + kk + 4];
                a[mf][3] = As[r0 + 8 * LDS + kk + 4];
                if (RA) {
#pragma unroll
                    for (int r = 0; r < 4; r++) a[mf][r] = tf32r(a[mf][r]);
                }
            }
#pragma unroll
            for (int nf = 0; nf < NF; nf++) {
                const int r0 = (wn * WNT + nf * 8 + lr) * LDS;
                b[nf][0] = Bs[r0 + kk];
                b[nf][1] = Bs[r0 + kk + 4];
            }
#pragma unroll
            for (int mf = 0; mf < MF; mf++)
#pragma unroll
                for (int nf = 0; nf < NF; nf++)
                    mma_tf32(acc[mf][nf], a[mf], b[nf]);
        }
        __syncthreads();
    }

    const int mb = m0 + wm * WMT, nb = n0 + wn * WNT;

    if (MODE == 7) {
        // fp32 tf32r(relu(acc+bias)) stores + fused row-norm reduction.
        float* spart = sm;                    // reuse (all smem reads done)
#pragma unroll
        for (int mf = 0; mf < MF; mf++) {
            const int gr0 = mb + mf * 16 + lr, gr1 = gr0 + 8;
            float ss0 = 0.f, ss1 = 0.f;       // sumsq of this warp's col block
#pragma unroll
            for (int nf = 0; nf < NF; nf++) {
                const int gc = nb + nf * 8 + 2 * lc;
                const float* d = acc[mf][nf];
                float v0 = fmaxf(d[0] + bias[gc], 0.f);
                float v1 = fmaxf(d[1] + bias[gc + 1], 0.f);
                float v2 = fmaxf(d[2] + bias[gc], 0.f);
                float v3 = fmaxf(d[3] + bias[gc + 1], 0.f);
                *reinterpret_cast<float2*>(&Cb[(size_t)gr0 * Nfull + gc]) =
                    make_float2(tf32r(v0), tf32r(v1));
                *reinterpret_cast<float2*>(&Cb[(size_t)gr1 * Nfull + gc]) =
                    make_float2(tf32r(v2), tf32r(v3));
                ss0 += v0 * v0 + v1 * v1;
                ss1 += v2 * v2 + v3 * v3;
            }
            ss0 += __shfl_xor_sync(~0u, ss0, 1); ss0 += __shfl_xor_sync(~0u, ss0, 2);
            ss1 += __shfl_xor_sync(~0u, ss1, 1); ss1 += __shfl_xor_sync(~0u, ss1, 2);
            if (lc == 0) {
                int rl0 = wm * WMT + mf * 16 + lr;
                spart[wn * 128 + rl0]     = ss0;
                spart[wn * 128 + rl0 + 8] = ss1;
            }
        }
        __syncthreads();
        if (tid < 128) {
            int row = m0 + tid;               // grid (1,128): full coverage
            float sf = spart[tid] + spart[128 + tid];          // wn 0,1 = f cols
            float sg = spart[256 + tid] + spart[384 + tid];    // wn 2,3 = g cols
            partial[row] = sqrtf(sf);
            atomicMax(&maxg[row >> 12], __float_as_int(sqrtf(sg)));
        }
    } else if (MODE == 5) {
        __nv_bfloat16* Ct = (__nv_bfloat16*)C;
#pragma unroll
        for (int mf = 0; mf < MF; mf++) {
            const int gr0 = mb + mf * 16 + lr, gr1 = gr0 + 8;
#pragma unroll
            for (int nf = 0; nf < NF; nf++) {
                const int gc = nb + nf * 8 + 2 * lc;
                const float* d = acc[mf][nf];
                float v0 = fmaxf(d[0] + bias[gc], 0.f);
                float v1 = fmaxf(d[1] + bias[gc + 1], 0.f);
                float v2 = fmaxf(d[2] + bias[gc], 0.f);
                float v3 = fmaxf(d[3] + bias[gc + 1], 0.f);
                size_t b0 = ((size_t)(gr0 >> 12) * Nfull);
                size_t b1 = ((size_t)(gr1 >> 12) * Nfull);
                Ct[(b0 + gc)     * 4096 + (gr0 & 4095)] = __float2bfloat16_rn(v0);
                Ct[(b0 + gc + 1) * 4096 + (gr0 & 4095)] = __float2bfloat16_rn(v1);
                Ct[(b1 + gc)     * 4096 + (gr1 & 4095)] = __float2bfloat16_rn(v2);
                Ct[(b1 + gc + 1) * 4096 + (gr1 & 4095)] = __float2bfloat16_rn(v3);
            }
        }
    } else {  // MODE 6
        __nv_bfloat16* Pb = (__nv_bfloat16*)C + (size_t)bz * sC;
        float* spart = sm;                    // reuse smem (all reads done)
        const float Mg = __int_as_float(maxg[bz]);
        const int grow_base = bz * 4096;
#pragma unroll
        for (int mf = 0; mf < MF; mf++) {
            const int gr0 = mb + mf * 16 + lr, gr1 = gr0 + 8;
            const float M0 = normf[grow_base + gr0] * Mg;
            const float M1 = normf[grow_base + gr1] * Mg;
            float s0 = 0.f, s1 = 0.f;
#pragma unroll
            for (int nf = 0; nf < NF; nf++) {
                const int gc = nb + nf * 8 + 2 * lc;
                const float* d = acc[mf][nf];
                float e0 = __expf(d[0] - M0), e1 = __expf(d[1] - M0);
                float e2 = __expf(d[2] - M1), e3 = __expf(d[3] - M1);
                __nv_bfloat162 h0 = __floats2bfloat162_rn(e0, e1);
                __nv_bfloat162 h1 = __floats2bfloat162_rn(e2, e3);
                *reinterpret_cast<uint32_t*>(&Pb[(size_t)gr0 * Nfull + gc]) =
                    *reinterpret_cast<uint32_t*>(&h0);
                *reinterpret_cast<uint32_t*>(&Pb[(size_t)gr1 * Nfull + gc]) =
                    *reinterpret_cast<uint32_t*>(&h1);
                s0 += e0 + e1;
                s1 += e2 + e3;
            }
            s0 += __shfl_xor_sync(~0u, s0, 1); s0 += __shfl_xor_sync(~0u, s0, 2);
            s1 += __shfl_xor_sync(~0u, s1, 1); s1 += __shfl_xor_sync(~0u, s1, 2);
            if (lc == 0) {
                int rl0 = wm * WMT + mf * 16 + lr;
                spart[wn * 128 + rl0]     = s0;
                spart[wn * 128 + rl0 + 8] = s1;
            }
        }
        __syncthreads();
        if (tid < 128) {
            float s = spart[tid] + spart[128 + tid] + spart[256 + tid] + spart[384 + tid];
            partial[(size_t)blockIdx.x * M_TOT + grow_base + m0 + tid] = s;
        }
    }
}

// ---------------------------------------------------------------------------
// bf16 GEMM (final): out = gamma[n]*((p @ hT^T)/rowsum[m]) + V.
// BK=64 halfs, 2-stage cp.async (72KB smem -> 2 CTAs/SM, 16 warps).
// ---------------------------------------------------------------------------
__global__ __launch_bounds__(256, 2) void gemm_bf16_o(
    const __nv_bfloat16* __restrict__ A, const __nv_bfloat16* __restrict__ Bm,
    float* __restrict__ C, int M, int Nfull, int K,
    const float* __restrict__ gamma, const float* __restrict__ vres,
    const float* __restrict__ rowsum, long sA, long sB, long sC, long sV)
{
    constexpr int NT = 128, LDA = 36;
    constexpr int BKH = 64;
    constexpr int WMT = 64, WNT = 32, MF = 4, NF = 4;
    constexpr int ASZ = 128 * LDA, BUF = ASZ + NT * LDA;

    extern __shared__ uint32_t smu[];
    const int tid = threadIdx.x, wid = tid >> 5, lane = tid & 31;
    const int lr = lane >> 2, lc = lane & 3;
    const int bz = blockIdx.z;

    A  += (size_t)bz * sA;
    Bm += (size_t)bz * sB;
    float* Cb = C + (size_t)bz * sC;
    const float* vres_b = vres + (size_t)bz * sV;
    const float* rs_b   = rowsum + (size_t)bz * M;

    const int m0 = blockIdx.y * 128, n0 = blockIdx.x * NT;
    const int wm = wid & 1, wn = wid >> 1;
    const uint32_t sbase = smem_u32(smu);

    float acc[MF][NF][4];
#pragma unroll
    for (int i = 0; i < MF; i++)
#pragma unroll
        for (int j = 0; j < NF; j++)
#pragma unroll
            for (int r = 0; r < 4; r++) acc[i][j][r] = 0.f;

    auto stage = [&](int k0, int buf) {
#pragma unroll
        for (int l = 0; l < 4; l++) {
            int idx = tid + l * 256;
            int r = idx >> 3, q = idx & 7;
            CP16(sbase + (uint32_t)(buf * BUF + r * LDA + q * 4) * 4,
                 A + (size_t)(m0 + r) * K + k0 + q * 8);
        }
#pragma unroll
        for (int l = 0; l < 4; l++) {
            int idx = tid + l * 256;
            int r = idx >> 3, q = idx & 7;
            CP16(sbase + (uint32_t)(buf * BUF + ASZ + r * LDA + q * 4) * 4,
                 Bm + (size_t)(n0 + r) * K + k0 + q * 8);
        }
        CP_COMMIT();
    };

    const int T = K / BKH;
    stage(0, 0);
    for (int t = 0; t < T; t++) {
        if (t + 1 < T) { stage((t + 1) * BKH, (t + 1) & 1); CP_WAIT1(); }
        else            { CP_WAIT0(); }
        __syncthreads();

        const uint32_t* As = smu + (t & 1) * BUF;
        const uint32_t* Bs = As + ASZ;
#pragma unroll
        for (int ks = 0; ks < 4; ks++) {
            const int kk = ks * 8 + lc;
            uint32_t a[MF][4], b[NF][2];
#pragma unroll
            for (int mf = 0; mf < MF; mf++) {
                const int r0 = (wm * WMT + mf * 16 + lr) * LDA;
                a[mf][0] = As[r0 + kk];
                a[mf][1] = As[r0 + 8 * LDA + kk];
                a[mf][2] = As[r0 + kk + 4];
                a[mf][3] = As[r0 + 8 * LDA + kk + 4];
            }
#pragma unroll
            for (int nf = 0; nf < NF; nf++) {
                const int r0 = (wn * WNT + nf * 8 + lr) * LDA;
                b[nf][0] = Bs[r0 + kk];
                b[nf][1] = Bs[r0 + kk + 4];
            }
#pragma unroll
            for (int mf = 0; mf < MF; mf++)
#pragma unroll
                for (int nf = 0; nf < NF; nf++)
                    mma_bf16(acc[mf][nf], a[mf], b[nf]);
        }
        __syncthreads();
    }

    const int mb = m0 + wm * WMT, nb = n0 + wn * WNT;
#pragma unroll
    for (int mf = 0; mf < MF; mf++) {
        const int gr0 = mb + mf * 16 + lr, gr1 = gr0 + 8;
        const float inv0 = 1.f / rs_b[gr0], inv1 = 1.f / rs_b[gr1];
#pragma unroll
        for (int nf = 0; nf < NF; nf++) {
            const int gc = nb + nf * 8 + 2 * lc;
            const float* d = acc[mf][nf];
            float2 vr0 = *reinterpret_cast<const float2*>(&vres_b[(size_t)gr0 * Nfull + gc]);
            float2 vr1 = *reinterpret_cast<const float2*>(&vres_b[(size_t)gr1 * Nfull + gc]);
            float2 gg  = *reinterpret_cast<const float2*>(&gamma[gc]);
            *reinterpret_cast<float2*>(&Cb[(size_t)gr0 * Nfull + gc]) =
                make_float2(fmaf(gg.x, d[0] * inv0, vr0.x), fmaf(gg.y, d[1] * inv0, vr0.y));
            *reinterpret_cast<float2*>(&Cb[(size_t)gr1 * Nfull + gc]) =
                make_float2(fmaf(gg.x, d[2] * inv1, vr1.x), fmaf(gg.y, d[3] * inv1, vr1.y));
        }
    }
}

// ---------------------------------------------------------------------------
// Small kernels
// ---------------------------------------------------------------------------
__global__ void transpose_k(const float* __restrict__ in, float* __restrict__ out,
                            int R, int Ccols)
{
    __shared__ float t[32][33];
    const int c0 = blockIdx.x * 32, r0 = blockIdx.y * 32;
    const int x = threadIdx.x, y = threadIdx.y;
#pragma unroll
    for (int i = 0; i < 32; i += 8)
        t[y + i][x] = in[(size_t)(r0 + y + i) * Ccols + c0 + x];
    __syncthreads();
#pragma unroll
    for (int i = 0; i < 32; i += 8)
        out[(size_t)(c0 + y + i) * R + r0 + x] = tf32r(t[x][y + i]);
}

// Transpose two [F,C] weights into stacked wfgT [128,512] in one launch.
__global__ void transpose2_k(const float* __restrict__ inA, const float* __restrict__ inB,
                             float* __restrict__ out, int R, int Ccols)
{
    __shared__ float t[32][33];
    const float* in = blockIdx.z ? inB : inA;
    float* o = out + (size_t)blockIdx.z * Ccols * R;   // slab offset (64*512)
    const int c0 = blockIdx.x * 32, r0 = blockIdx.y * 32;
    const int x = threadIdx.x, y = threadIdx.y;
#pragma unroll
    for (int i = 0; i < 32; i += 8)
        t[y + i][x] = in[(size_t)(r0 + y + i) * Ccols + c0 + x];
    __syncthreads();
#pragma unroll
    for (int i = 0; i < 32; i += 8)
        o[(size_t)(c0 + y + i) * R + r0 + x] = tf32r(t[x][y + i]);
}

// bias concat + maxg zero, one launch
__global__ void prep_k(const float* __restrict__ a, const float* __restrict__ b,
                       float* __restrict__ out, int* __restrict__ mg)
{
    int t = threadIdx.x;
    out[t] = (t < 64) ? a[t] : b[t - 64];
    if (t < B_) mg[t] = 0;
}

__global__ __launch_bounds__(256) void reduce_rs_k(const float* __restrict__ partial,
                                                   float* __restrict__ rs)
{
    int i = blockIdx.x * 256 + threadIdx.x;
    float s = 0.f;
#pragma unroll
    for (int nt = 0; nt < 32; nt++) s += partial[(size_t)nt * M_TOT + i];
    rs[i] = s;
}

// ---------------------------------------------------------------------------
extern "C" void kernel_launch(void* const* d_in, const int* in_sizes, int n_in,
                              void* d_out, int out_size)
{
    const float* V  = (const float*)d_in[0];
    const float* Wf = (const float*)d_in[1];
    const float* bf = (const float*)d_in[2];
    const float* Wg = (const float*)d_in[3];
    const float* bg = (const float*)d_in[4];
    const float* Wh = (const float*)d_in[5];
    const float* bh = (const float*)d_in[6];
    const float* gm = (const float*)d_in[7];
    float* out = (float*)d_out;

    float *fgP, *partP, *rsP, *normfP, *bfgP, *wfgT, *whT;
    int* maxgP;
    __nv_bfloat16 *hTP, *pP;
    cudaGetSymbolAddress((void**)&fgP,   g_fg);
    cudaGetSymbolAddress((void**)&hTP,   g_hT);
    cudaGetSymbolAddress((void**)&pP,    g_p);
    cudaGetSymbolAddress((void**)&partP, g_part);
    cudaGetSymbolAddress((void**)&rsP,   g_rs);
    cudaGetSymbolAddress((void**)&normfP,g_normf);
    cudaGetSymbolAddress((void**)&maxgP, g_maxg);
    cudaGetSymbolAddress((void**)&bfgP,  g_bfg);
    cudaGetSymbolAddress((void**)&wfgT,  g_wfgT);
    cudaGetSymbolAddress((void**)&whT,   g_whT);

    const int SM_TF = 2 * (128 + 128) * 36 * 4;   // 73728 B
    const int SM_BF = 2 * (128 + 128) * 36 * 4;   // 73728 B

    cudaFuncSetAttribute(gemm_tf32<128, 7, true>,
                         cudaFuncAttributeMaxDynamicSharedMemorySize, SM_TF);
    cudaFuncSetAttribute(gemm_tf32<128, 5, true>,
                         cudaFuncAttributeMaxDynamicSharedMemorySize, SM_TF);
    cudaFuncSetAttribute(gemm_tf32<128, 6, false>,
                         cudaFuncAttributeMaxDynamicSharedMemorySize, SM_TF);
    cudaFuncSetAttribute(gemm_bf16_o,
                         cudaFuncAttributeMaxDynamicSharedMemorySize, SM_BF);

    dim3 blk(256);
    dim3 tb(32, 8);

    // Stacked [WfT; WgT] -> wfgT (one launch, z=2); whT; bias concat + maxg=0.
    transpose2_k<<<dim3(C_ / 32, F_ / 32, 2), tb>>>(Wf, Wg, wfgT, F_, C_);
    transpose_k<<<dim3(F_ / 32, F_ / 32), tb>>>(Wh, whT, F_, F_);
    prep_k<<<1, 128>>>(bf, bg, bfgP, maxgP);

    // fg = relu(V @ [Wf|Wg] + [bf|bg]) + fused row norms (normf, maxg)
    gemm_tf32<128, 7, true><<<dim3(1, 128, 1), blk, SM_TF>>>(
        V, wfgT, fgP, M_TOT, 128, F_, F_, F_, bfgP,
        nullptr, maxgP, normfP, 0, 0, 0);

    // hT[b][f][n] = bf16(relu(V@Wh+bh)) transposed per batch
    gemm_tf32<128, 5, true><<<dim3(4, 128, 1), blk, SM_TF>>>(
        V, whT, (float*)hTP, M_TOT, F_, F_, F_, F_, bh,
        nullptr, nullptr, nullptr, 0, 0, 0);

    // scores + fused exp: p = bf16(exp(f@g^T - M_row)), partial rowsums
    gemm_tf32<128, 6, false><<<dim3(32, 32, B_), blk, SM_TF>>>(
        fgP, fgP + 64, (float*)pP, N_, N_, C_, 128, 128, nullptr,
        normfP, maxgP, partP,
        (long)N_ * 128, (long)N_ * 128, (long)N_ * N_);

    // rowsum = sum of 32 n-tile partials (deterministic)
    reduce_rs_k<<<M_TOT / 256, blk>>>(partP, rsP);

    // out = gamma * (p @ h / rowsum) + V
    gemm_bf16_o<<<dim3(4, 32, B_), blk, SM_BF>>>(
        pP, hTP, out, N_, F_, N_, gm, V, rsP,
        (long)N_ * N_, (long)F_ * N_, (long)N_ * F_, (long)N_ * F_);
}

// round 14
// speedup vs baseline: 10.3648x; 1.0875x over previous
// R13: (1) o-GEMM inner loop -> ldmatrix.m8n8.x4 fragment loads (6 LDSM vs
// 24 LDS per k16 step; bit-identical data). (2) fg MODE 7 tail: block-reduce
// ||g|| max in smem, single atomicMax per CTA (was 128 -> contended L2 atoms).
// Everything else identical to R11.
#include <cuda_runtime.h>
#include <cuda_bf16.h>
#include <cstdint>
#include <math.h>

#define B_    4
#define N_    4096
#define F_    512
#define C_    64
#define M_TOT (B_ * N_)   // 16384

// ---------------- scratch (allocation-free) ----------------
__device__ float g_fg[(size_t)M_TOT * 128];              //  8 MiB [f|g] tf32
__device__ __nv_bfloat16 g_hT[(size_t)M_TOT * F_];       // 16 MiB, [B][F][N] bf16
__device__ __nv_bfloat16 g_p[(size_t)M_TOT * N_];        // 128 MiB exp(bf16)
__device__ float g_part[(size_t)32 * M_TOT];             //  2 MiB partial rowsums
__device__ float g_rs[M_TOT];
__device__ float g_normf[M_TOT];
__device__ int   g_maxg[B_];
__device__ float g_bfg[128];
__device__ float g_wfgT[128 * F_];                       // stacked [WfT; WgT]
__device__ float g_whT[F_ * F_];

// ---------------- helpers ----------------
__device__ __forceinline__ float tf32r(float x) {
    uint32_t u;
    asm("cvt.rna.tf32.f32 %0, %1;" : "=r"(u) : "f"(x));
    return __uint_as_float(u);
}
__device__ __forceinline__ uint32_t smem_u32(const void* p) {
    uint32_t a;
    asm("{ .reg .u64 t; cvta.to.shared.u64 t, %1; cvt.u32.u64 %0, t; }" : "=r"(a) : "l"(p));
    return a;
}
#define CP16(dst, src) \
    asm volatile("cp.async.ca.shared.global [%0], [%1], 16;" :: "r"(dst), "l"(src))
#define CP_COMMIT() asm volatile("cp.async.commit_group;" ::: "memory")
#define CP_WAIT1()  asm volatile("cp.async.wait_group 1;" ::: "memory")
#define CP_WAIT0()  asm volatile("cp.async.wait_group 0;" ::: "memory")
#define LDSM_X4(r0, r1, r2, r3, addr) \
    asm volatile("ldmatrix.sync.aligned.m8n8.x4.shared.b16 {%0,%1,%2,%3}, [%4];" \
        : "=r"(r0), "=r"(r1), "=r"(r2), "=r"(r3) : "r"(addr))

__device__ __forceinline__ void mma_tf32(float* d, const float* a, const float* b) {
    asm volatile(
        "mma.sync.aligned.m16n8k8.row.col.f32.tf32.tf32.f32 "
        "{%0,%1,%2,%3}, {%4,%5,%6,%7}, {%8,%9}, {%0,%1,%2,%3};"
        : "+f"(d[0]), "+f"(d[1]), "+f"(d[2]), "+f"(d[3])
        : "r"(__float_as_uint(a[0])), "r"(__float_as_uint(a[1])),
          "r"(__float_as_uint(a[2])), "r"(__float_as_uint(a[3])),
          "r"(__float_as_uint(b[0])), "r"(__float_as_uint(b[1])));
}
__device__ __forceinline__ void mma_bf16(float* d, const uint32_t* a, const uint32_t* b) {
    asm volatile(
        "mma.sync.aligned.m16n8k16.row.col.f32.bf16.bf16.f32 "
        "{%0,%1,%2,%3}, {%4,%5,%6,%7}, {%8,%9}, {%0,%1,%2,%3};"
        : "+f"(d[0]), "+f"(d[1]), "+f"(d[2]), "+f"(d[3])
        : "r"(a[0]), "r"(a[1]), "r"(a[2]), "r"(a[3]), "r"(b[0]), "r"(b[1]));
}

// ---------------------------------------------------------------------------
// tf32 GEMM: C[M, Nfull] = A[M,K] @ B^T, B stored [Nfull rows, K] with row
// stride ldB; A row stride ldA. BK=32, LDS=36 floats, 2-stage cp.async,
// 2 CTAs/SM. RA: round A frags to tf32 in-register.
// MODE 5: bf16 relu(acc+bias) written transposed per batch (h path).
// MODE 6: p = bf16(exp(acc - normf[row]*maxg[bz])); partial rowsums out.
// MODE 7: fp32 tf32r(relu(acc+bias)) -> C, PLUS fused row norms:
//         partial[row] = ||f_row||, atomicMax(maxg[batch], max||g_row||) 1/CTA.
// ---------------------------------------------------------------------------
template <int NT, int MODE, bool RA>
__global__ __launch_bounds__(256, 2) void gemm_tf32(
    const float* __restrict__ A, const float* __restrict__ Bm, float* __restrict__ C,
    int M, int Nfull, int K, int ldA, int ldB,
    const float* __restrict__ bias,
    const float* __restrict__ normf, int* __restrict__ maxg,
    float* __restrict__ partial,
    long sA, long sB, long sC)
{
    constexpr int BK = 32, LDS = 36;
    constexpr int WN_WARPS = 4, WM_WARPS = 2;
    constexpr int WMT = 64;
    constexpr int WNT = NT / WN_WARPS;
    constexpr int MF = 4, NF = WNT / 8;
    constexpr int ASZ = 128 * LDS, BUF = ASZ + NT * LDS;
    constexpr int LB = NT / 32;

    extern __shared__ float sm[];
    const int tid = threadIdx.x, wid = tid >> 5, lane = tid & 31;
    const int lr = lane >> 2, lc = lane & 3;
    const int bz = blockIdx.z;

    A  += (size_t)bz * sA;
    Bm += (size_t)bz * sB;
    float* Cb = C;
    if (MODE == 7) Cb = C + (size_t)bz * sC;

    const int m0 = blockIdx.y * 128, n0 = blockIdx.x * NT;
    const int wm = wid % WM_WARPS, wn = wid / WM_WARPS;
    const uint32_t sbase = smem_u32(sm);

    float acc[MF][NF][4];
#pragma unroll
    for (int i = 0; i < MF; i++)
#pragma unroll
        for (int j = 0; j < NF; j++)
#pragma unroll
            for (int r = 0; r < 4; r++) acc[i][j][r] = 0.f;

    auto stage = [&](int k0, int buf) {
#pragma unroll
        for (int l = 0; l < 4; l++) {                 // A: 128 rows x 32 floats
            int idx = tid + l * 256;
            int r = idx >> 3, q = idx & 7;
            CP16(sbase + (uint32_t)(buf * BUF + r * LDS + q * 4) * 4,
                 A + (size_t)(m0 + r) * ldA + k0 + q * 4);
        }
#pragma unroll
        for (int l = 0; l < LB; l++) {                // B: NT rows x 32 floats
            int idx = tid + l * 256;
            int r = idx >> 3, q = idx & 7;
            CP16(sbase + (uint32_t)(buf * BUF + ASZ + r * LDS + q * 4) * 4,
                 Bm + (size_t)(n0 + r) * ldB + k0 + q * 4);
        }
        CP_COMMIT();
    };

    const int T = K / BK;
    stage(0, 0);
    for (int t = 0; t < T; t++) {
        if (t + 1 < T) { stage((t + 1) * BK, (t + 1) & 1); CP_WAIT1(); }
        else            { CP_WAIT0(); }
        __syncthreads();

        const float* As = sm + (t & 1) * BUF;
        const float* Bs = As + ASZ;
#pragma unroll
        for (int ks = 0; ks < BK / 8; ks++) {
            const int kk = ks * 8 + lc;
            float a[MF][4], b[NF][2];
#pragma unroll
            for (int mf = 0; mf < MF; mf++) {
                const int r0 = (wm * WMT + mf * 16 + lr) * LDS;
                a[mf][0] = As[r0 + kk];
                a[mf][1] = As[r0 + 8 * LDS + kk];
                a[mf][2] = As[r0 + kk + 4];
                a[mf][3] = As[r0 + 8 * LDS + kk + 4];
                if (RA) {
#pragma unroll
                    for (int r = 0; r < 4; r++) a[mf][r] = tf32r(a[mf][r]);
                }
            }
#pragma unroll
            for (int nf = 0; nf < NF; nf++) {
                const int r0 = (wn * WNT + nf * 8 + lr) * LDS;
                b[nf][0] = Bs[r0 + kk];
                b[nf][1] = Bs[r0 + kk + 4];
            }
#pragma unroll
            for (int mf = 0; mf < MF; mf++)
#pragma unroll
                for (int nf = 0; nf < NF; nf++)
                    mma_tf32(acc[mf][nf], a[mf], b[nf]);
        }
        __syncthreads();
    }

    const int mb = m0 + wm * WMT, nb = n0 + wn * WNT;

    if (MODE == 7) {
        // fp32 tf32r(relu(acc+bias)) stores + fused row-norm reduction.
        float* spart = sm;                    // reuse (all smem reads done)
#pragma unroll
        for (int mf = 0; mf < MF; mf++) {
            const int gr0 = mb + mf * 16 + lr, gr1 = gr0 + 8;
            float ss0 = 0.f, ss1 = 0.f;       // sumsq of this warp's col block
#pragma unroll
            for (int nf = 0; nf < NF; nf++) {
                const int gc = nb + nf * 8 + 2 * lc;
                const float* d = acc[mf][nf];
                float v0 = fmaxf(d[0] + bias[gc], 0.f);
                float v1 = fmaxf(d[1] + bias[gc + 1], 0.f);
                float v2 = fmaxf(d[2] + bias[gc], 0.f);
                float v3 = fmaxf(d[3] + bias[gc + 1], 0.f);
                *reinterpret_cast<float2*>(&Cb[(size_t)gr0 * Nfull + gc]) =
                    make_float2(tf32r(v0), tf32r(v1));
                *reinterpret_cast<float2*>(&Cb[(size_t)gr1 * Nfull + gc]) =
                    make_float2(tf32r(v2), tf32r(v3));
                ss0 += v0 * v0 + v1 * v1;
                ss1 += v2 * v2 + v3 * v3;
            }
            ss0 += __shfl_xor_sync(~0u, ss0, 1); ss0 += __shfl_xor_sync(~0u, ss0, 2);
            ss1 += __shfl_xor_sync(~0u, ss1, 1); ss1 += __shfl_xor_sync(~0u, ss1, 2);
            if (lc == 0) {
                int rl0 = wm * WMT + mf * 16 + lr;
                spart[wn * 128 + rl0]     = ss0;
                spart[wn * 128 + rl0 + 8] = ss1;
            }
        }
        __syncthreads();
        if (tid < 128) {
            int row = m0 + tid;               // grid (1,128): full coverage
            float sf = spart[tid] + spart[128 + tid];          // wn 0,1 = f cols
            float sg = spart[256 + tid] + spart[384 + tid];    // wn 2,3 = g cols
            partial[row] = sqrtf(sf);
            spart[512 + tid] = sqrtf(sg);     // stage for block max-reduce
        }
        __syncthreads();
        if (tid < 32) {                       // block max over 128, 1 atomic/CTA
            float mg = fmaxf(fmaxf(spart[512 + tid],       spart[512 + tid + 32]),
                             fmaxf(spart[512 + tid + 64],  spart[512 + tid + 96]));
#pragma unroll
            for (int o = 16; o; o >>= 1) mg = fmaxf(mg, __shfl_xor_sync(~0u, mg, o));
            if (tid == 0) atomicMax(&maxg[m0 >> 12], __float_as_int(mg));
        }
    } else if (MODE == 5) {
        __nv_bfloat16* Ct = (__nv_bfloat16*)C;
#pragma unroll
        for (int mf = 0; mf < MF; mf++) {
            const int gr0 = mb + mf * 16 + lr, gr1 = gr0 + 8;
#pragma unroll
            for (int nf = 0; nf < NF; nf++) {
                const int gc = nb + nf * 8 + 2 * lc;
                const float* d = acc[mf][nf];
                float v0 = fmaxf(d[0] + bias[gc], 0.f);
                float v1 = fmaxf(d[1] + bias[gc + 1], 0.f);
                float v2 = fmaxf(d[2] + bias[gc], 0.f);
                float v3 = fmaxf(d[3] + bias[gc + 1], 0.f);
                size_t b0 = ((size_t)(gr0 >> 12) * Nfull);
                size_t b1 = ((size_t)(gr1 >> 12) * Nfull);
                Ct[(b0 + gc)     * 4096 + (gr0 & 4095)] = __float2bfloat16_rn(v0);
                Ct[(b0 + gc + 1) * 4096 + (gr0 & 4095)] = __float2bfloat16_rn(v1);
                Ct[(b1 + gc)     * 4096 + (gr1 & 4095)] = __float2bfloat16_rn(v2);
                Ct[(b1 + gc + 1) * 4096 + (gr1 & 4095)] = __float2bfloat16_rn(v3);
            }
        }
    } else {  // MODE 6
        __nv_bfloat16* Pb = (__nv_bfloat16*)C + (size_t)bz * sC;
        float* spart = sm;                    // reuse smem (all reads done)
        const float Mg = __int_as_float(maxg[bz]);
        const int grow_base = bz * 4096;
#pragma unroll
        for (int mf = 0; mf < MF; mf++) {
            const int gr0 = mb + mf * 16 + lr, gr1 = gr0 + 8;
            const float M0 = normf[grow_base + gr0] * Mg;
            const float M1 = normf[grow_base + gr1] * Mg;
            float s0 = 0.f, s1 = 0.f;
#pragma unroll
            for (int nf = 0; nf < NF; nf++) {
                const int gc = nb + nf * 8 + 2 * lc;
                const float* d = acc[mf][nf];
                float e0 = __expf(d[0] - M0), e1 = __expf(d[1] - M0);
                float e2 = __expf(d[2] - M1), e3 = __expf(d[3] - M1);
                __nv_bfloat162 h0 = __floats2bfloat162_rn(e0, e1);
                __nv_bfloat162 h1 = __floats2bfloat162_rn(e2, e3);
                *reinterpret_cast<uint32_t*>(&Pb[(size_t)gr0 * Nfull + gc]) =
                    *reinterpret_cast<uint32_t*>(&h0);
                *reinterpret_cast<uint32_t*>(&Pb[(size_t)gr1 * Nfull + gc]) =
                    *reinterpret_cast<uint32_t*>(&h1);
                s0 += e0 + e1;
                s1 += e2 + e3;
            }
            s0 += __shfl_xor_sync(~0u, s0, 1); s0 += __shfl_xor_sync(~0u, s0, 2);
            s1 += __shfl_xor_sync(~0u, s1, 1); s1 += __shfl_xor_sync(~0u, s1, 2);
            if (lc == 0) {
                int rl0 = wm * WMT + mf * 16 + lr;
                spart[wn * 128 + rl0]     = s0;
                spart[wn * 128 + rl0 + 8] = s1;
            }
        }
        __syncthreads();
        if (tid < 128) {
            float s = spart[tid] + spart[128 + tid] + spart[256 + tid] + spart[384 + tid];
            partial[(size_t)blockIdx.x * M_TOT + grow_base + m0 + tid] = s;
        }
    }
}

// ---------------------------------------------------------------------------
// bf16 GEMM (final): out = gamma[n]*((p @ hT^T)/rowsum[m]) + V.
// BK=64 halfs, 2-stage cp.async, 2 CTAs/SM; ldmatrix fragment loads.
// ---------------------------------------------------------------------------
__global__ __launch_bounds__(256, 2) void gemm_bf16_o(
    const __nv_bfloat16* __restrict__ A, const __nv_bfloat16* __restrict__ Bm,
    float* __restrict__ C, int M, int Nfull, int K,
    const float* __restrict__ gamma, const float* __restrict__ vres,
    const float* __restrict__ rowsum, long sA, long sB, long sC, long sV)
{
    constexpr int NT = 128, LDA = 36;                 // uint32 pairs per row
    constexpr int BKH = 64;
    constexpr int WMT = 64, WNT = 32, MF = 4, NF = 4;
    constexpr int ASZ = 128 * LDA, BUF = ASZ + NT * LDA;   // uint32 units

    extern __shared__ uint32_t smu[];
    const int tid = threadIdx.x, wid = tid >> 5, lane = tid & 31;
    const int lr = lane >> 2, lc = lane & 3;
    const int bz = blockIdx.z;

    A  += (size_t)bz * sA;
    Bm += (size_t)bz * sB;
    float* Cb = C + (size_t)bz * sC;
    const float* vres_b = vres + (size_t)bz * sV;
    const float* rs_b   = rowsum + (size_t)bz * M;

    const int m0 = blockIdx.y * 128, n0 = blockIdx.x * NT;
    const int wm = wid & 1, wn = wid >> 1;
    const uint32_t sbase = smem_u32(smu);

    // Per-lane ldmatrix byte offsets within a buffer.
    // A x4 (one 16x16 frag): lanes 0-15 -> rows m0-15 @k0; 16-31 -> rows @+16B.
    const int a_row = wm * WMT + (lane & 15);
    const uint32_t a_off0 = (uint32_t)a_row * (LDA * 4) + ((lane >> 4) * 16);
    // B x4 (two n8k16 frags): row = ((l>>4)&1)*8 + (l&7); koff = ((l>>3)&1)*16.
    const int b_row = wn * WNT + (((lane >> 4) & 1) * 8) + (lane & 7);
    const uint32_t b_off0 = (uint32_t)(ASZ * 4) + (uint32_t)b_row * (LDA * 4) +
                            (((lane >> 3) & 1) * 16);

    float acc[MF][NF][4];
#pragma unroll
    for (int i = 0; i < MF; i++)
#pragma unroll
        for (int j = 0; j < NF; j++)
#pragma unroll
            for (int r = 0; r < 4; r++) acc[i][j][r] = 0.f;

    auto stage = [&](int k0, int buf) {
#pragma unroll
        for (int l = 0; l < 4; l++) {
            int idx = tid + l * 256;
            int r = idx >> 3, q = idx & 7;
            CP16(sbase + (uint32_t)(buf * BUF + r * LDA + q * 4) * 4,
                 A + (size_t)(m0 + r) * K + k0 + q * 8);
        }
#pragma unroll
        for (int l = 0; l < 4; l++) {
            int idx = tid + l * 256;
            int r = idx >> 3, q = idx & 7;
            CP16(sbase + (uint32_t)(buf * BUF + ASZ + r * LDA + q * 4) * 4,
                 Bm + (size_t)(n0 + r) * K + k0 + q * 8);
        }
        CP_COMMIT();
    };

    const int T = K / BKH;
    stage(0, 0);
    for (int t = 0; t < T; t++) {
        if (t + 1 < T) { stage((t + 1) * BKH, (t + 1) & 1); CP_WAIT1(); }
        else            { CP_WAIT0(); }
        __syncthreads();

        const uint32_t bufbase = sbase + (uint32_t)((t & 1) * BUF) * 4;
#pragma unroll
        for (int ks = 0; ks < 4; ks++) {      // 4 k16 steps per tile (32B each)
            uint32_t a[MF][4], b[NF][2];
#pragma unroll
            for (int mf = 0; mf < MF; mf++)
                LDSM_X4(a[mf][0], a[mf][1], a[mf][2], a[mf][3],
                        bufbase + a_off0 + (uint32_t)(mf * 16 * LDA * 4) + ks * 32);
#pragma unroll
            for (int np = 0; np < 2; np++)    // each covers 2 n8k16 frags
                LDSM_X4(b[2 * np][0], b[2 * np][1], b[2 * np + 1][0], b[2 * np + 1][1],
                        bufbase + b_off0 + (uint32_t)(np * 16 * LDA * 4) + ks * 32);
#pragma unroll
            for (int mf = 0; mf < MF; mf++)
#pragma unroll
                for (int nf = 0; nf < NF; nf++)
                    mma_bf16(acc[mf][nf], a[mf], b[nf]);
        }
        __syncthreads();
    }

    const int mb = m0 + wm * WMT, nb = n0 + wn * WNT;
#pragma unroll
    for (int mf = 0; mf < MF; mf++) {
        const int gr0 = mb + mf * 16 + lr, gr1 = gr0 + 8;
        const float inv0 = 1.f / rs_b[gr0], inv1 = 1.f / rs_b[gr1];
#pragma unroll
        for (int nf = 0; nf < NF; nf++) {
            const int gc = nb + nf * 8 + 2 * lc;
            const float* d = acc[mf][nf];
            float2 vr0 = *reinterpret_cast<const float2*>(&vres_b[(size_t)gr0 * Nfull + gc]);
            float2 vr1 = *reinterpret_cast<const float2*>(&vres_b[(size_t)gr1 * Nfull + gc]);
            float2 gg  = *reinterpret_cast<const float2*>(&gamma[gc]);
            *reinterpret_cast<float2*>(&Cb[(size_t)gr0 * Nfull + gc]) =
                make_float2(fmaf(gg.x, d[0] * inv0, vr0.x), fmaf(gg.y, d[1] * inv0, vr0.y));
            *reinterpret_cast<float2*>(&Cb[(size_t)gr1 * Nfull + gc]) =
                make_float2(fmaf(gg.x, d[2] * inv1, vr1.x), fmaf(gg.y, d[3] * inv1, vr1.y));
        }
    }
}

// ---------------------------------------------------------------------------
// Small kernels
// ---------------------------------------------------------------------------
__global__ void transpose_k(const float* __restrict__ in, float* __restrict__ out,
                            int R, int Ccols)
{
    __shared__ float t[32][33];
    const int c0 = blockIdx.x * 32, r0 = blockIdx.y * 32;
    const int x = threadIdx.x, y = threadIdx.y;
#pragma unroll
    for (int i = 0; i < 32; i += 8)
        t[y + i][x] = in[(size_t)(r0 + y + i) * Ccols + c0 + x];
    __syncthreads();
#pragma unroll
    for (int i = 0; i < 32; i += 8)
        out[(size_t)(c0 + y + i) * R + r0 + x] = tf32r(t[x][y + i]);
}

// Transpose two [F,C] weights into stacked wfgT [128,512] in one launch.
__global__ void transpose2_k(const float* __restrict__ inA, const float* __restrict__ inB,
                             float* __restrict__ out, int R, int Ccols)
{
    __shared__ float t[32][33];
    const float* in = blockIdx.z ? inB : inA;
    float* o = out + (size_t)blockIdx.z * Ccols * R;   // slab offset (64*512)
    const int c0 = blockIdx.x * 32, r0 = blockIdx.y * 32;
    const int x = threadIdx.x, y = threadIdx.y;
#pragma unroll
    for (int i = 0; i < 32; i += 8)
        t[y + i][x] = in[(size_t)(r0 + y + i) * Ccols + c0 + x];
    __syncthreads();
#pragma unroll
    for (int i = 0; i < 32; i += 8)
        o[(size_t)(c0 + y + i) * R + r0 + x] = tf32r(t[x][y + i]);
}

// bias concat + maxg zero, one launch
__global__ void prep_k(const float* __restrict__ a, const float* __restrict__ b,
                       float* __restrict__ out, int* __restrict__ mg)
{
    int t = threadIdx.x;
    out[t] = (t < 64) ? a[t] : b[t - 64];
    if (t < B_) mg[t] = 0;
}

__global__ __launch_bounds__(256) void reduce_rs_k(const float* __restrict__ partial,
                                                   float* __restrict__ rs)
{
    int i = blockIdx.x * 256 + threadIdx.x;
    float s = 0.f;
#pragma unroll
    for (int nt = 0; nt < 32; nt++) s += partial[(size_t)nt * M_TOT + i];
    rs[i] = s;
}

// ---------------------------------------------------------------------------
extern "C" void kernel_launch(void* const* d_in, const int* in_sizes, int n_in,
                              void* d_out, int out_size)
{
    const float* V  = (const float*)d_in[0];
    const float* Wf = (const float*)d_in[1];
    const float* bf = (const float*)d_in[2];
    const float* Wg = (const float*)d_in[3];
    const float* bg = (const float*)d_in[4];
    const float* Wh = (const float*)d_in[5];
    const float* bh = (const float*)d_in[6];
    const float* gm = (const float*)d_in[7];
    float* out = (float*)d_out;

    float *fgP, *partP, *rsP, *normfP, *bfgP, *wfgT, *whT;
    int* maxgP;
    __nv_bfloat16 *hTP, *pP;
    cudaGetSymbolAddress((void**)&fgP,   g_fg);
    cudaGetSymbolAddress((void**)&hTP,   g_hT);
    cudaGetSymbolAddress((void**)&pP,    g_p);
    cudaGetSymbolAddress((void**)&partP, g_part);
    cudaGetSymbolAddress((void**)&rsP,   g_rs);
    cudaGetSymbolAddress((void**)&normfP,g_normf);
    cudaGetSymbolAddress((void**)&maxgP, g_maxg);
    cudaGetSymbolAddress((void**)&bfgP,  g_bfg);
    cudaGetSymbolAddress((void**)&wfgT,  g_wfgT);
    cudaGetSymbolAddress((void**)&whT,   g_whT);

    const int SM_TF = 2 * (128 + 128) * 36 * 4;   // 73728 B
    const int SM_BF = 2 * (128 + 128) * 36 * 4;   // 73728 B

    cudaFuncSetAttribute(gemm_tf32<128, 7, true>,
                         cudaFuncAttributeMaxDynamicSharedMemorySize, SM_TF);
    cudaFuncSetAttribute(gemm_tf32<128, 5, true>,
                         cudaFuncAttributeMaxDynamicSharedMemorySize, SM_TF);
    cudaFuncSetAttribute(gemm_tf32<128, 6, false>,
                         cudaFuncAttributeMaxDynamicSharedMemorySize, SM_TF);
    cudaFuncSetAttribute(gemm_bf16_o,
                         cudaFuncAttributeMaxDynamicSharedMemorySize, SM_BF);

    dim3 blk(256);
    dim3 tb(32, 8);

    // Stacked [WfT; WgT] -> wfgT (one launch, z=2); whT; bias concat + maxg=0.
    transpose2_k<<<dim3(C_ / 32, F_ / 32, 2), tb>>>(Wf, Wg, wfgT, F_, C_);
    transpose_k<<<dim3(F_ / 32, F_ / 32), tb>>>(Wh, whT, F_, F_);
    prep_k<<<1, 128>>>(bf, bg, bfgP, maxgP);

    // fg = relu(V @ [Wf|Wg] + [bf|bg]) + fused row norms (normf, maxg)
    gemm_tf32<128, 7, true><<<dim3(1, 128, 1), blk, SM_TF>>>(
        V, wfgT, fgP, M_TOT, 128, F_, F_, F_, bfgP,
        nullptr, maxgP, normfP, 0, 0, 0);

    // hT[b][f][n] = bf16(relu(V@Wh+bh)) transposed per batch
    gemm_tf32<128, 5, true><<<dim3(4, 128, 1), blk, SM_TF>>>(
        V, whT, (float*)hTP, M_TOT, F_, F_, F_, F_, bh,
        nullptr, nullptr, nullptr, 0, 0, 0);

    // scores + fused exp: p = bf16(exp(f@g^T - M_row)), partial rowsums
    gemm_tf32<128, 6, false><<<dim3(32, 32, B_), blk, SM_TF>>>(
        fgP, fgP + 64, (float*)pP, N_, N_, C_, 128, 128, nullptr,
        normfP, maxgP, partP,
        (long)N_ * 128, (long)N_ * 128, (long)N_ * N_);

    // rowsum = sum of 32 n-tile partials (deterministic)
    reduce_rs_k<<<M_TOT / 256, blk>>>(partP, rsP);

    // out = gamma * (p @ h / rowsum) + V
    gemm_bf16_o<<<dim3(4, 32, B_), blk, SM_BF>>>(
        pP, hTP, out, N_, F_, N_, gm, V, rsP,
        (long)N_ * N_, (long)F_ * N_, (long)N_ * F_, (long)N_ * F_);
}